// round 13
// baseline (speedup 1.0000x reference)
#include <cuda_runtime.h>
#include <cuda_bf16.h>
#include <cuda_fp16.h>
#include <math.h>
#include <stdint.h>

// ---------------- problem constants ----------------
#define L_DIM   128
#define N_DIM   256
#define M_DIM   131072
#define IMG_BSTRIDE 8388608   // 64*131072

// Only n in {4w+1, 4w+2} feed the output. sel s in [0,128): n = 4*(s>>1)+1+(s&1).

// ---------------- scratch (static device memory; no allocs) ----------------
__device__ float g_part[256 * 16384];          // alignedT partials [stripe][sel-n][l]
__device__ float g_tline[2 * 64 * 64];         // [b][c][w]  ([l][w], l = b*64+c)
__device__ float g_pre1[2 * 64 * 64];          // [b][o][w]

// ---------------- MUFU-based fast math ----------------
__device__ __forceinline__ float mufu_sigmoid(float x) {
    float e;
    asm("ex2.approx.f32 %0, %1;" : "=f"(e) : "f"(-1.4426950408889634f * x));
    float r;
    asm("rcp.approx.f32 %0, %1;" : "=f"(r) : "f"(1.0f + e));
    return r;
}
__device__ __forceinline__ float efun(float dot, float an, float bn) {
    float d2 = fmaxf(an + bn - 2.f * dot, 0.f);
    float c;
    asm("sqrt.approx.f32 %0, %1;" : "=f"(c) : "f"(d2));
    float e;
    asm("ex2.approx.f32 %0, %1;" : "=f"(e) : "f"(-0.14426950408889634f * c));
    return 1e-4f * e;
}

// ---------------- warp MMA helpers ----------------
__device__ __forceinline__ uint32_t smem_u32(const void* p) {
    uint32_t a;
    asm("{ .reg .u64 t; cvta.to.shared.u64 t, %1; cvt.u32.u64 %0, t; }" : "=r"(a) : "l"(p));
    return a;
}
__device__ __forceinline__ void ldsm4(uint32_t* r, uint32_t a) {
    asm volatile("ldmatrix.sync.aligned.m8n8.x4.shared.b16 {%0,%1,%2,%3}, [%4];"
                 : "=r"(r[0]), "=r"(r[1]), "=r"(r[2]), "=r"(r[3]) : "r"(a));
}
__device__ __forceinline__ void ldsm4t(uint32_t* r, uint32_t a) {
    asm volatile("ldmatrix.sync.aligned.m8n8.x4.trans.shared.b16 {%0,%1,%2,%3}, [%4];"
                 : "=r"(r[0]), "=r"(r[1]), "=r"(r[2]), "=r"(r[3]) : "r"(a));
}
__device__ __forceinline__ void mma_bf16(float* d, const uint32_t* a,
                                         uint32_t b0, uint32_t b1) {
    asm volatile("mma.sync.aligned.m16n8k16.row.col.f32.bf16.bf16.f32 "
                 "{%0,%1,%2,%3}, {%4,%5,%6,%7}, {%8,%9}, {%0,%1,%2,%3};"
                 : "+f"(d[0]), "+f"(d[1]), "+f"(d[2]), "+f"(d[3])
                 : "r"(a[0]), "r"(a[1]), "r"(a[2]), "r"(a[3]), "r"(b0), "r"(b1));
}
__device__ __forceinline__ void mma_f16(float* d, const uint32_t* a,
                                        uint32_t b0, uint32_t b1) {
    asm volatile("mma.sync.aligned.m16n8k16.row.col.f32.f16.f16.f32 "
                 "{%0,%1,%2,%3}, {%4,%5,%6,%7}, {%8,%9}, {%0,%1,%2,%3};"
                 : "+f"(d[0]), "+f"(d[1]), "+f"(d[2]), "+f"(d[3])
                 : "r"(a[0]), "r"(a[1]), "r"(a[2]), "r"(a[3]), "r"(b0), "r"(b1));
}
__device__ __forceinline__ uint32_t pack_bf16(float lo, float hi) {
    uint32_t r;
    asm("cvt.rn.bf16x2.f32 %0, %1, %2;" : "=r"(r) : "f"(hi), "f"(lo));
    return r;
}
__device__ __forceinline__ uint32_t pack_f16(float lo, float hi) {
    uint32_t r;
    asm("cvt.rn.f16x2.f32 %0, %1, %2;" : "=r"(r) : "f"(hi), "f"(lo));
    return r;
}
__device__ __forceinline__ void cp_async16(uint32_t daddr, const void* gptr) {
    asm volatile("cp.async.ca.shared.global [%0], [%1], 16;"
                 :: "r"(daddr), "l"(gptr) : "memory");
}
__device__ __forceinline__ float bf16_hl(uint32_t u, int hi) {
    uint16_t h = hi ? (uint16_t)(u >> 16) : (uint16_t)(u & 0xFFFF);
    return __bfloat162float(__ushort_as_bfloat16(h));
}

// ================= K1: fused tensor-core pipeline (512 thr, s-split) ==========
// 128 CTAs x 512 thr, 1/SM. CTA = m-stripe of 1024 (8 chunks of 128 m).
// Warps: nw = w&7 picks 16 sel-n rows; sh = w>>3 picks s-parity (even/odd).
// Each warp accumulates its own acc2; stores to stripe = bid*2 + sh (256 total).
// smem: TEXT 34816 | STG0 @34816 (67584) | STG1 @102400 | IMGB @169984 (34816)
//   | TMP @204800 (8192) | BN2 @212992 | AN2 @213504 | total 214016
__global__ __launch_bounds__(512, 1) void k_fused(const float* __restrict__ img,
                                                  const float* __restrict__ text) {
    extern __shared__ char dsm[];
    const int TEXT = 0, STG0 = 34816, STG1 = 102400, IMGB = 169984,
              TMP = 204800, BN2 = 212992, AN2 = 213504;
    float* bn2s = (float*)(dsm + BN2);
    float* an2s = (float*)(dsm + AN2);

    int t = threadIdx.x, bid = blockIdx.x;
    int w = t >> 5, lane = t & 31;
    int nw = w & 7, sh = w >> 3;
    uint32_t sb = smem_u32(dsm);
    uint32_t sbi = sb + IMGB;

    // ---- build text tile [sel-n s][l-pair c2] bf16, pitch 272B ----
    for (int p = t; p < 8192; p += 512) {
        int s = p >> 6, c2 = p & 63;
        int n = 4 * (s >> 1) + 1 + (s & 1);
        *(uint32_t*)(dsm + TEXT + s * 272 + c2 * 4) =
            pack_bf16(__ldg(&text[(2 * c2) * 256 + n]),
                      __ldg(&text[(2 * c2 + 1) * 256 + n]));
    }

    // prologue: async-load chunk 0 fp32 into STG0 (rows=l, 32 uint4/row, pad 33)
    {
        const char* gb = (const char*)(img + (size_t)bid * 1024);
        #pragma unroll
        for (int r = 0; r < 8; r++) {
            int f = t + 512 * r;
            int row = f >> 5, q = f & 31;
            cp_async16(sb + STG0 + (uint32_t)(row * 33 + q) * 16u,
                       gb + (size_t)row * 524288 + q * 16);
        }
        asm volatile("cp.async.commit_group;" ::: "memory");
    }
    __syncthreads();

    // ---- an2 from the bf16 text tile ----
    if (t < 128) {
        float s = 0.f;
        #pragma unroll 8
        for (int c2 = 0; c2 < 64; c2++) {
            uint32_t u = *(uint32_t*)(dsm + TEXT + t * 272 + c2 * 4);
            float v0 = bf16_hl(u, 0), v1 = bf16_hl(u, 1);
            s = fmaf(v0, v0, fmaf(v1, v1, s));
        }
        an2s[t] = s;
    }

    float acc2[16][4];
    #pragma unroll
    for (int lt = 0; lt < 16; lt++)
        #pragma unroll
        for (int r = 0; r < 4; r++) acc2[lt][r] = 0.f;

    __syncthreads();
    float an2v0 = an2s[nw * 16 + (lane >> 2)];
    float an2v1 = an2s[nw * 16 + (lane >> 2) + 8];

    uint32_t a_addr = (uint32_t)(nw * 16 + (lane & 15)) * 272u
                    + (uint32_t)((lane >> 4) * 16);
    uint32_t b_row = (uint32_t)(lane & 15) * 272u;
    uint32_t b_colbase = (uint32_t)((lane >> 4) * 16);

    int c4 = t & 31;              // float4 column in convert
    int rp = t >> 5;              // row phase 0..15

    #pragma unroll 1
    for (int c = 0; c < 8; c++) {
        if (c < 7) {
            uint32_t dst = sb + (((c + 1) & 1) ? STG1 : STG0);
            const char* gb = (const char*)(img + (size_t)bid * 1024 + (c + 1) * 128);
            #pragma unroll
            for (int r = 0; r < 8; r++) {
                int f = t + 512 * r;
                int row = f >> 5, q = f & 31;
                cp_async16(dst + (uint32_t)(row * 33 + q) * 16u,
                           gb + (size_t)row * 524288 + q * 16);
            }
            asm volatile("cp.async.commit_group;" ::: "memory");
            asm volatile("cp.async.wait_group 1;" ::: "memory");
        } else {
            asm volatile("cp.async.wait_group 0;" ::: "memory");
        }
        __syncthreads();   // stage(c) visible; IMGB free (prev mma done)

        // ---- convert fp32 stage -> bf16 IMGB tile [l][m-pair], + bn2 ----
        {
            const char* stg = dsm + ((c & 1) ? STG1 : STG0);
            float s0 = 0.f, s1 = 0.f, s2 = 0.f, s3 = 0.f;
            #pragma unroll
            for (int i = 0; i < 8; i++) {
                int row = rp + 16 * i;
                float4 v = *(const float4*)(stg + row * 528 + c4 * 16);
                s0 = fmaf(v.x, v.x, s0);
                s1 = fmaf(v.y, v.y, s1);
                s2 = fmaf(v.z, v.z, s2);
                s3 = fmaf(v.w, v.w, s3);
                *(uint2*)(dsm + IMGB + row * 272 + c4 * 8) =
                    make_uint2(pack_bf16(v.x, v.y), pack_bf16(v.z, v.w));
            }
            ((float4*)(dsm + TMP))[t] = make_float4(s0, s1, s2, s3);
        }
        __syncthreads();
        if (t < 128) {
            float v = 0.f;
            #pragma unroll
            for (int q = 0; q < 16; q++)
                v += ((const float*)(dsm + TMP))[(q * 32 + (t >> 2)) * 4 + (t & 3)];
            bn2s[t] = v;
        }
        __syncthreads();   // IMGB + bn2 ready

        #pragma unroll 1
        for (int s = sh; s < 8; s += 2) {
            uint32_t scol = (uint32_t)(s * 32) + b_colbase;

            // ---- GEMM1: D[16 sel-n x 16 m], K=l=128; B via ldsm4t ----
            float c1[2][4];
            #pragma unroll
            for (int j = 0; j < 2; j++)
                #pragma unroll
                for (int r = 0; r < 4; r++) c1[j][r] = 0.f;

            #pragma unroll
            for (int kk = 0; kk < 8; kk++) {
                uint32_t a[4], bfr[4];
                ldsm4(a, sb + TEXT + a_addr + kk * 32u);
                ldsm4t(bfr, sbi + b_row + (uint32_t)(kk * 16) * 272u + scol);
                mma_bf16(c1[0], a, bfr[0], bfr[1]);
                mma_bf16(c1[1], a, bfr[2], bfr[3]);
            }

            // ---- epilogue: E in regs, repack as A frag for GEMM2 ----
            uint32_t a2[4];
            #pragma unroll
            for (int j = 0; j < 2; j++) {
                float2 bn = *(float2*)&bn2s[s * 16 + j * 8 + 2 * (lane & 3)];
                float e0 = efun(c1[j][0], an2v0, bn.x);
                float e1 = efun(c1[j][1], an2v0, bn.y);
                float e2 = efun(c1[j][2], an2v1, bn.x);
                float e3 = efun(c1[j][3], an2v1, bn.y);
                a2[2 * j]     = pack_bf16(e0, e1);
                a2[2 * j + 1] = pack_bf16(e2, e3);
            }

            // ---- GEMM2: acc2[sel-n, l] += E . img; B via ldsm4 (re-read) ----
            #pragma unroll
            for (int lb = 0; lb < 8; lb++) {
                uint32_t b2r[4];
                ldsm4(b2r, sbi + b_row + (uint32_t)(lb * 16) * 272u + scol);
                mma_bf16(acc2[2 * lb],     a2, b2r[0], b2r[2]);
                mma_bf16(acc2[2 * lb + 1], a2, b2r[1], b2r[3]);
            }
        }
        __syncthreads();   // done reading IMGB before next convert
    }

    // store partials: g_part[stripe][sel-n][l], stripe = bid*2 + sh
    int nbase = nw * 16 + (lane >> 2);
    size_t stripe = (size_t)(bid * 2 + sh);
    #pragma unroll
    for (int lt = 0; lt < 16; lt++) {
        int l = lt * 8 + 2 * (lane & 3);
        size_t base = stripe * 16384 + (size_t)nbase * 128 + l;
        *(float2*)&g_part[base] = make_float2(acc2[lt][0], acc2[lt][1]);
        *(float2*)&g_part[base + 8 * 128] = make_float2(acc2[lt][2], acc2[lt][3]);
    }
}

// ================= K2: split-K reduce partials + interp -> t_line =============
// 128 blocks x 256 thr. out-idx = B*16 + (t&15) in [0,2048) float4 units.
// split = t>>4 (0..15), each sums 16 of the 256 stripes.
__global__ void k_redtl() {
    __shared__ float4 red[256];
    int t = threadIdx.x, B = blockIdx.x;
    int out = B * 16 + (t & 15);
    int split = t >> 4;
    int w = out >> 5, l4 = out & 31;
    const float4* p4 = (const float4*)g_part;
    float4 s = make_float4(0.f, 0.f, 0.f, 0.f);
    #pragma unroll 4
    for (int st = split * 16; st < split * 16 + 16; st++) {
        float4 a = p4[(size_t)st * 4096 + (2 * w) * 32 + l4];
        float4 b = p4[(size_t)st * 4096 + (2 * w + 1) * 32 + l4];
        s.x += a.x + b.x; s.y += a.y + b.y;
        s.z += a.z + b.z; s.w += a.w + b.w;
    }
    red[t] = s;
    __syncthreads();
    if (t < 16) {
        float4 s2 = red[t];
        #pragma unroll
        for (int q = 1; q < 16; q++) {
            float4 r = red[t + 16 * q];
            s2.x += r.x; s2.y += r.y; s2.z += r.z; s2.w += r.w;
        }
        int o2 = B * 16 + t;
        int w2 = o2 >> 5, l42 = o2 & 31;
        g_tline[(4 * l42 + 0) * 64 + w2] = 0.5f * s2.x;
        g_tline[(4 * l42 + 1) * 64 + w2] = 0.5f * s2.y;
        g_tline[(4 * l42 + 2) * 64 + w2] = 0.5f * s2.z;
        g_tline[(4 * l42 + 3) * 64 + w2] = 0.5f * s2.w;
    }
}

// ================= K3: pre1 = b1 + W1a @ t_line =================
__global__ void k_pre1(const float* __restrict__ w1, const float* __restrict__ b1) {
    int f = blockIdx.x * 256 + threadIdx.x;   // f = b*4096 + o*64 + w
    int b = f >> 12, o = (f >> 6) & 63, w = f & 63;
    float s = __ldg(&b1[o]);
    #pragma unroll 8
    for (int c = 0; c < 64; c++)
        s = fmaf(__ldg(&w1[o * 128 + c]), g_tline[(b * 64 + c) * 64 + w], s);
    g_pre1[f] = s;
}

// ================= K4: per-voxel MLP + gated blend (fp16 mma) =================
// 1024 blocks x 512 thr; 256 voxels/block (two sequential 128-vox tiles).
// smem: X16@0 (17408) | H16@17408 | GT@0 (64x528, after X/H dead) |
//       W1@34816 | W2@44032 | PRE@53248 | TL@70656 | total 88064
#define SVB 272
#define SWB 144
__global__ __launch_bounds__(512, 2) void k_mlp(const float* __restrict__ img,
                                                const float* __restrict__ w1,
                                                const float* __restrict__ w2,
                                                const float* __restrict__ b2,
                                                float* __restrict__ out) {
    extern __shared__ char dsm[];
    const int X16 = 0, H16 = 17408, GT = 0, W1O = 34816, W2O = 44032,
              PRE = 53248, TL = 70656;
    uint32_t sb = smem_u32(dsm);

    int t = threadIdx.x;
    int bb = blockIdx.x >> 9;
    int m0 = (blockIdx.x & 511) << 8;
    int w = t >> 5, lane = t & 31;
    int obase = (w & 3) * 16;
    int vwbase = (w >> 2) * 32;

    // ---- stage weights (fp16), pre1, tline (fp32) once per block ----
    for (int f = t; f < 2048; f += 512) {
        int o = f >> 5, c2 = f & 31;
        float2 a = *(const float2*)&w1[o * 128 + 64 + 2 * c2];
        *(uint32_t*)(dsm + W1O + o * SWB + c2 * 4) = pack_f16(a.x, a.y);
        float2 b = *(const float2*)&w2[o * 64 + 2 * c2];
        *(uint32_t*)(dsm + W2O + o * SWB + c2 * 4) = pack_f16(b.x, b.y);
    }
    for (int f = t; f < 1024; f += 512) {
        int o = f >> 4, w4 = f & 15;
        *(float4*)(dsm + PRE + o * 272 + w4 * 16) =
            *(const float4*)&g_pre1[bb * 4096 + o * 64 + w4 * 4];
        *(float4*)(dsm + TL + o * 272 + w4 * 16) =
            *(const float4*)&g_tline[bb * 4096 + o * 64 + w4 * 4];
    }

    int orow = obase + (lane >> 2);
    int vcol = 2 * (lane & 3);
    float bv0 = __ldg(&b2[orow]), bv1 = __ldg(&b2[orow + 8]);

    uint32_t aw_addr = (uint32_t)(obase + (lane & 15)) * SWB + (uint32_t)((lane >> 4) * 16);
    uint32_t bx_row = (uint32_t)(lane & 15) * SVB;
    uint32_t bx_col = (uint32_t)(vwbase * 2 + (lane >> 4) * 16);

    #pragma unroll 1
    for (int tile = 0; tile < 2; tile++) {
        int m0t = m0 + tile * 128;

        // ---- load x tile -> fp16 smem (wide) ----
        for (int f = t; f < 1024; f += 512) {
            int cc = f >> 3, v8 = f & 7;
            const float4* gp = (const float4*)(img + (size_t)(bb * 64 + cc) * M_DIM + m0t)
                             + v8 * 4;
            float4 x0 = gp[0], x1 = gp[1], x2 = gp[2], x3 = gp[3];
            *(uint4*)(dsm + X16 + cc * SVB + v8 * 32) =
                make_uint4(pack_f16(x0.x, x0.y), pack_f16(x0.z, x0.w),
                           pack_f16(x1.x, x1.y), pack_f16(x1.z, x1.w));
            *(uint4*)(dsm + X16 + cc * SVB + v8 * 32 + 16) =
                make_uint4(pack_f16(x2.x, x2.y), pack_f16(x2.z, x2.w),
                           pack_f16(x3.x, x3.y), pack_f16(x3.z, x3.w));
        }
        __syncthreads();   // X ready

        // ---- acc init from PRE smem ----
        float acc[4][4];
        #pragma unroll
        for (int j = 0; j < 4; j++) {
            int ws = (vwbase + 8 * j + vcol) & 63;
            float2 p0 = *(const float2*)(dsm + PRE + orow * 272 + ws * 4);
            float2 p1 = *(const float2*)(dsm + PRE + (orow + 8) * 272 + ws * 4);
            acc[j][0] = p0.x; acc[j][1] = p0.y;
            acc[j][2] = p1.x; acc[j][3] = p1.y;
        }

        // ---- layer 1: h = pre1 + W1b @ x ----
        #pragma unroll
        for (int k = 0; k < 4; k++) {
            uint32_t a[4];
            ldsm4(a, sb + W1O + aw_addr + k * 32u);
            #pragma unroll
            for (int q = 0; q < 2; q++) {
                uint32_t bx[4];
                ldsm4t(bx, sb + X16 + bx_row + (uint32_t)(16 * k) * SVB + bx_col + q * 32u);
                mma_f16(acc[2 * q],     a, bx[0], bx[1]);
                mma_f16(acc[2 * q + 1], a, bx[2], bx[3]);
            }
        }

        // ---- relu -> fp16 H smem ----
        #pragma unroll
        for (int j = 0; j < 4; j++) {
            int vox0 = vwbase + 8 * j + vcol;
            *(uint32_t*)(dsm + H16 + orow * SVB + vox0 * 2) =
                pack_f16(fmaxf(acc[j][0], 0.f), fmaxf(acc[j][1], 0.f));
            *(uint32_t*)(dsm + H16 + (orow + 8) * SVB + vox0 * 2) =
                pack_f16(fmaxf(acc[j][2], 0.f), fmaxf(acc[j][3], 0.f));
        }
        __syncthreads();

        // ---- layer 2: g = b2 + W2 @ H ----
        #pragma unroll
        for (int j = 0; j < 4; j++) {
            acc[j][0] = bv0; acc[j][1] = bv0;
            acc[j][2] = bv1; acc[j][3] = bv1;
        }
        #pragma unroll
        for (int k = 0; k < 4; k++) {
            uint32_t a[4];
            ldsm4(a, sb + W2O + aw_addr + k * 32u);
            #pragma unroll
            for (int q = 0; q < 2; q++) {
                uint32_t bh[4];
                ldsm4t(bh, sb + H16 + bx_row + (uint32_t)(16 * k) * SVB + bx_col + q * 32u);
                mma_f16(acc[2 * q],     a, bh[0], bh[1]);
                mma_f16(acc[2 * q + 1], a, bh[2], bh[3]);
            }
        }
        __syncthreads();   // all H reads done before GT overwrites that region

        // ---- gates -> smem GT [o][vox] fp32, pitch 528 ----
        #pragma unroll
        for (int j = 0; j < 4; j++) {
            int vox0 = vwbase + 8 * j + vcol;
            *(float2*)(dsm + GT + orow * 528 + vox0 * 4) =
                make_float2(mufu_sigmoid(acc[j][0]), mufu_sigmoid(acc[j][1]));
            *(float2*)(dsm + GT + (orow + 8) * 528 + vox0 * 4) =
                make_float2(mufu_sigmoid(acc[j][2]), mufu_sigmoid(acc[j][3]));
        }
        __syncthreads();

        // ---- coalesced blend pass: warp w owns rows 4w..4w+3 ----
        #pragma unroll
        for (int jr = 0; jr < 4; jr++) {
            int row = w * 4 + jr;
            size_t gidx = (size_t)(bb * 64 + row) * M_DIM + m0t + lane * 4;
            float4 xv = *(const float4*)(img + gidx);
            float4 gv = *(const float4*)(dsm + GT + row * 528 + lane * 16);
            float4 tv = *(const float4*)(dsm + TL + row * 272 + (lane & 15) * 16);
            float4 ov;
            ov.x = fmaf(gv.x, tv.x - xv.x, xv.x);
            ov.y = fmaf(gv.y, tv.y - xv.y, xv.y);
            ov.z = fmaf(gv.z, tv.z - xv.z, xv.z);
            ov.w = fmaf(gv.w, tv.w - xv.w, xv.w);
            *(float4*)(out + gidx) = ov;
        }
        __syncthreads();   // GT reads done before next tile's X load reuses region
    }
}

// ================= launch =================
extern "C" void kernel_launch(void* const* d_in, const int* in_sizes, int n_in,
                              void* d_out, int out_size) {
    const float* text = (const float*)d_in[0];
    const float* img  = (const float*)d_in[1];
    const float* w1   = (const float*)d_in[2];
    const float* b1   = (const float*)d_in[3];
    const float* w2   = (const float*)d_in[4];
    const float* b2   = (const float*)d_in[5];
    float* out = (float*)d_out;

    cudaFuncSetAttribute(k_fused, cudaFuncAttributeMaxDynamicSharedMemorySize, 214016);
    cudaFuncSetAttribute(k_mlp,   cudaFuncAttributeMaxDynamicSharedMemorySize, 88064);

    k_fused<<<128, 512, 214016>>>(img, text);
    k_redtl<<<128, 256>>>();
    k_pre1 <<<32, 256>>>(w1, b1);
    k_mlp  <<<1024, 512, 88064>>>(img, w1, w2, b2, out);
}

// round 14
// speedup vs baseline: 1.0572x; 1.0572x over previous
#include <cuda_runtime.h>
#include <cuda_bf16.h>
#include <cuda_fp16.h>
#include <math.h>
#include <stdint.h>

// ---------------- problem constants ----------------
#define L_DIM   128
#define N_DIM   256
#define M_DIM   131072
#define IMG_BSTRIDE 8388608   // 64*131072

// Only n in {4w+1, 4w+2} feed the output. sel s in [0,128): n = 4*(s>>1)+1+(s&1).

// ---------------- scratch (static device memory; no allocs) ----------------
__device__ float g_part[128 * 16384];          // alignedT partials [stripe][sel-n][l]
__device__ float g_tline[2 * 64 * 64];         // [b][c][w]  ([l][w], l = b*64+c)
__device__ float g_pre1[2 * 64 * 64];          // [b][o][w]

// ---------------- MUFU-based fast math ----------------
__device__ __forceinline__ float mufu_sigmoid(float x) {
    float e;
    asm("ex2.approx.f32 %0, %1;" : "=f"(e) : "f"(-1.4426950408889634f * x));
    float r;
    asm("rcp.approx.f32 %0, %1;" : "=f"(r) : "f"(1.0f + e));
    return r;
}
__device__ __forceinline__ float efun(float dot, float an, float bn) {
    float d2 = fmaxf(an + bn - 2.f * dot, 0.f);
    float c;
    asm("sqrt.approx.f32 %0, %1;" : "=f"(c) : "f"(d2));
    float e;
    asm("ex2.approx.f32 %0, %1;" : "=f"(e) : "f"(-0.14426950408889634f * c));
    return 1e-4f * e;
}

// ---------------- warp MMA helpers ----------------
__device__ __forceinline__ uint32_t smem_u32(const void* p) {
    uint32_t a;
    asm("{ .reg .u64 t; cvta.to.shared.u64 t, %1; cvt.u32.u64 %0, t; }" : "=r"(a) : "l"(p));
    return a;
}
__device__ __forceinline__ void ldsm4(uint32_t* r, uint32_t a) {
    asm volatile("ldmatrix.sync.aligned.m8n8.x4.shared.b16 {%0,%1,%2,%3}, [%4];"
                 : "=r"(r[0]), "=r"(r[1]), "=r"(r[2]), "=r"(r[3]) : "r"(a));
}
__device__ __forceinline__ void ldsm4t(uint32_t* r, uint32_t a) {
    asm volatile("ldmatrix.sync.aligned.m8n8.x4.trans.shared.b16 {%0,%1,%2,%3}, [%4];"
                 : "=r"(r[0]), "=r"(r[1]), "=r"(r[2]), "=r"(r[3]) : "r"(a));
}
__device__ __forceinline__ uint32_t movm(uint32_t a) {
    uint32_t d;
    asm volatile("movmatrix.sync.aligned.m8n8.trans.b16 %0, %1;" : "=r"(d) : "r"(a));
    return d;
}
__device__ __forceinline__ void mma_bf16(float* d, const uint32_t* a,
                                         uint32_t b0, uint32_t b1) {
    asm volatile("mma.sync.aligned.m16n8k16.row.col.f32.bf16.bf16.f32 "
                 "{%0,%1,%2,%3}, {%4,%5,%6,%7}, {%8,%9}, {%0,%1,%2,%3};"
                 : "+f"(d[0]), "+f"(d[1]), "+f"(d[2]), "+f"(d[3])
                 : "r"(a[0]), "r"(a[1]), "r"(a[2]), "r"(a[3]), "r"(b0), "r"(b1));
}
__device__ __forceinline__ void mma_f16(float* d, const uint32_t* a,
                                        uint32_t b0, uint32_t b1) {
    asm volatile("mma.sync.aligned.m16n8k16.row.col.f32.f16.f16.f32 "
                 "{%0,%1,%2,%3}, {%4,%5,%6,%7}, {%8,%9}, {%0,%1,%2,%3};"
                 : "+f"(d[0]), "+f"(d[1]), "+f"(d[2]), "+f"(d[3])
                 : "r"(a[0]), "r"(a[1]), "r"(a[2]), "r"(a[3]), "r"(b0), "r"(b1));
}
__device__ __forceinline__ uint32_t pack_bf16(float lo, float hi) {
    uint32_t r;
    asm("cvt.rn.bf16x2.f32 %0, %1, %2;" : "=r"(r) : "f"(hi), "f"(lo));
    return r;
}
__device__ __forceinline__ uint32_t pack_f16(float lo, float hi) {
    uint32_t r;
    asm("cvt.rn.f16x2.f32 %0, %1, %2;" : "=r"(r) : "f"(hi), "f"(lo));
    return r;
}
__device__ __forceinline__ void cp_async16(uint32_t daddr, const void* gptr) {
    asm volatile("cp.async.ca.shared.global [%0], [%1], 16;"
                 :: "r"(daddr), "l"(gptr) : "memory");
}
__device__ __forceinline__ float bf16_hl(uint32_t u, int hi) {
    uint16_t h = hi ? (uint16_t)(u >> 16) : (uint16_t)(u & 0xFFFF);
    return __bfloat162float(__ushort_as_bfloat16(h));
}

// ================= K1: fully-fused tensor-core pipeline (R11 winner) ==========
// 128 CTAs x 256 thr, 1/SM. CTA = m-stripe of 1024 (8 chunks of 128 m).
// GEMM1 B-frags saved; GEMM2 B-frags derived via movmatrix (no re-ldsm).
__global__ __launch_bounds__(256, 1) void k_fused(const float* __restrict__ img,
                                                  const float* __restrict__ text) {
    extern __shared__ char dsm[];
    const int TEXT = 0, STG0 = 34816, STG1 = 102400, IMGB = 169984,
              TMP = 204800, BN2 = 208896, AN2 = 209408;
    float* bn2s = (float*)(dsm + BN2);
    float* an2s = (float*)(dsm + AN2);

    int t = threadIdx.x, bid = blockIdx.x;
    int w = t >> 5, lane = t & 31;
    uint32_t sb = smem_u32(dsm);
    uint32_t sbi = sb + IMGB;

    // ---- build text tile [sel-n s][l-pair c2] bf16, pitch 272B ----
    for (int p = t; p < 8192; p += 256) {
        int s = p >> 6, c2 = p & 63;
        int n = 4 * (s >> 1) + 1 + (s & 1);
        *(uint32_t*)(dsm + TEXT + s * 272 + c2 * 4) =
            pack_bf16(__ldg(&text[(2 * c2) * 256 + n]),
                      __ldg(&text[(2 * c2 + 1) * 256 + n]));
    }

    // prologue: async-load chunk 0 fp32 into STG0 (rows=l, 32 uint4/row, pad 33)
    {
        const char* gb = (const char*)(img + (size_t)bid * 1024);
        #pragma unroll
        for (int r = 0; r < 16; r++) {
            int f = t + 256 * r;
            int row = f >> 5, q = f & 31;
            cp_async16(sb + STG0 + (uint32_t)(row * 33 + q) * 16u,
                       gb + (size_t)row * 524288 + q * 16);
        }
        asm volatile("cp.async.commit_group;" ::: "memory");
    }
    __syncthreads();

    // ---- an2 from the bf16 text tile ----
    if (t < 128) {
        float s = 0.f;
        #pragma unroll 8
        for (int c2 = 0; c2 < 64; c2++) {
            uint32_t u = *(uint32_t*)(dsm + TEXT + t * 272 + c2 * 4);
            float v0 = bf16_hl(u, 0), v1 = bf16_hl(u, 1);
            s = fmaf(v0, v0, fmaf(v1, v1, s));
        }
        an2s[t] = s;
    }
    __syncthreads();

    // ---- hoist text A fragments (invariant) into registers ----
    uint32_t a_addr = (uint32_t)(w * 16 + (lane & 15)) * 272u
                    + (uint32_t)((lane >> 4) * 16);
    uint32_t atex[8][4];
    #pragma unroll
    for (int kk = 0; kk < 8; kk++)
        ldsm4(atex[kk], sb + TEXT + a_addr + kk * 32u);

    float acc2[16][4];
    #pragma unroll
    for (int lt = 0; lt < 16; lt++)
        #pragma unroll
        for (int r = 0; r < 4; r++) acc2[lt][r] = 0.f;

    float an2v0 = an2s[w * 16 + (lane >> 2)];
    float an2v1 = an2s[w * 16 + (lane >> 2) + 8];

    uint32_t b_row = (uint32_t)(lane & 15) * 272u;
    uint32_t b_colbase = (uint32_t)((lane >> 4) * 16);

    int c4 = t & 31;              // this thread's float4 column in convert
    int rp = t >> 5;              // row phase

    #pragma unroll 1
    for (int c = 0; c < 8; c++) {
        if (c < 7) {
            uint32_t dst = sb + (((c + 1) & 1) ? STG1 : STG0);
            const char* gb = (const char*)(img + (size_t)bid * 1024 + (c + 1) * 128);
            #pragma unroll
            for (int r = 0; r < 16; r++) {
                int f = t + 256 * r;
                int row = f >> 5, q = f & 31;
                cp_async16(dst + (uint32_t)(row * 33 + q) * 16u,
                           gb + (size_t)row * 524288 + q * 16);
            }
            asm volatile("cp.async.commit_group;" ::: "memory");
            asm volatile("cp.async.wait_group 1;" ::: "memory");
        } else {
            asm volatile("cp.async.wait_group 0;" ::: "memory");
        }
        __syncthreads();   // stage(c) visible; IMGB free (prev mma done)

        // ---- convert fp32 stage -> bf16 IMGB tile [l][m-pair], + bn2 (wide) --
        {
            const char* stg = dsm + ((c & 1) ? STG1 : STG0);
            float s0 = 0.f, s1 = 0.f, s2 = 0.f, s3 = 0.f;
            #pragma unroll 8
            for (int i = 0; i < 16; i++) {
                int row = rp + 8 * i;
                float4 v = *(const float4*)(stg + row * 528 + c4 * 16);
                s0 = fmaf(v.x, v.x, s0);
                s1 = fmaf(v.y, v.y, s1);
                s2 = fmaf(v.z, v.z, s2);
                s3 = fmaf(v.w, v.w, s3);
                *(uint2*)(dsm + IMGB + row * 272 + c4 * 8) =
                    make_uint2(pack_bf16(v.x, v.y), pack_bf16(v.z, v.w));
            }
            ((float4*)(dsm + TMP))[t] = make_float4(s0, s1, s2, s3);
        }
        __syncthreads();
        if (t < 128) {
            float v = 0.f;
            #pragma unroll
            for (int q = 0; q < 8; q++)
                v += ((const float*)(dsm + TMP))[(q * 32 + (t >> 2)) * 4 + (t & 3)];
            bn2s[t] = v;
        }
        __syncthreads();   // IMGB + bn2 ready

        #pragma unroll 1
        for (int s = 0; s < 8; s++) {
            uint32_t scol = (uint32_t)(s * 32) + b_colbase;

            // ---- GEMM1: D[16 sel-n x 16 m], K=l=128; B via ldsm4t, SAVED ----
            float c1[2][4];
            #pragma unroll
            for (int j = 0; j < 2; j++)
                #pragma unroll
                for (int r = 0; r < 4; r++) c1[j][r] = 0.f;

            uint32_t bsave[8][4];
            #pragma unroll
            for (int kk = 0; kk < 8; kk++) {
                ldsm4t(bsave[kk], sbi + b_row + (uint32_t)(kk * 16) * 272u + scol);
                mma_bf16(c1[0], atex[kk], bsave[kk][0], bsave[kk][1]);
                mma_bf16(c1[1], atex[kk], bsave[kk][2], bsave[kk][3]);
            }

            // ---- epilogue: E in regs, repack as A frag for GEMM2 ----
            uint32_t a2[4];
            #pragma unroll
            for (int j = 0; j < 2; j++) {
                float2 bn = *(float2*)&bn2s[s * 16 + j * 8 + 2 * (lane & 3)];
                float e0 = efun(c1[j][0], an2v0, bn.x);
                float e1 = efun(c1[j][1], an2v0, bn.y);
                float e2 = efun(c1[j][2], an2v1, bn.x);
                float e3 = efun(c1[j][3], an2v1, bn.y);
                a2[2 * j]     = pack_bf16(e0, e1);
                a2[2 * j + 1] = pack_bf16(e2, e3);
            }

            // ---- GEMM2: acc2[sel-n, l] += E . img; B = movmatrix(bsave) ----
            #pragma unroll
            for (int lb = 0; lb < 8; lb++) {
                uint32_t m0r = movm(bsave[lb][0]);
                uint32_t m1r = movm(bsave[lb][1]);
                uint32_t m2r = movm(bsave[lb][2]);
                uint32_t m3r = movm(bsave[lb][3]);
                mma_bf16(acc2[2 * lb],     a2, m0r, m2r);
                mma_bf16(acc2[2 * lb + 1], a2, m1r, m3r);
            }
        }
        __syncthreads();   // done reading IMGB before next convert
    }

    // store partials: g_part[bid][sel-n][l]
    int nbase = w * 16 + (lane >> 2);
    #pragma unroll
    for (int lt = 0; lt < 16; lt++) {
        int l = lt * 8 + 2 * (lane & 3);
        size_t base = (size_t)bid * 16384 + (size_t)nbase * 128 + l;
        *(float2*)&g_part[base] = make_float2(acc2[lt][0], acc2[lt][1]);
        *(float2*)&g_part[base + 8 * 128] = make_float2(acc2[lt][2], acc2[lt][3]);
    }
}

// ================= K2: split-K reduce partials + interp -> t_line =============
// 128 blocks x 128 thr (R11 winner).
__global__ void k_redtl() {
    __shared__ float4 red[128];
    int t = threadIdx.x, B = blockIdx.x;
    int out = B * 16 + (t & 15);
    int split = t >> 4;
    int w = out >> 5, l4 = out & 31;
    const float4* p4 = (const float4*)g_part;
    float4 s = make_float4(0.f, 0.f, 0.f, 0.f);
    #pragma unroll 4
    for (int st = split * 16; st < split * 16 + 16; st++) {
        float4 a = p4[(size_t)st * 4096 + (2 * w) * 32 + l4];
        float4 b = p4[(size_t)st * 4096 + (2 * w + 1) * 32 + l4];
        s.x += a.x + b.x; s.y += a.y + b.y;
        s.z += a.z + b.z; s.w += a.w + b.w;
    }
    red[t] = s;
    __syncthreads();
    if (t < 16) {
        float4 s2 = red[t];
        #pragma unroll
        for (int q = 1; q < 8; q++) {
            float4 r = red[t + 16 * q];
            s2.x += r.x; s2.y += r.y; s2.z += r.z; s2.w += r.w;
        }
        int o2 = B * 16 + t;
        int w2 = o2 >> 5, l42 = o2 & 31;
        g_tline[(4 * l42 + 0) * 64 + w2] = 0.5f * s2.x;
        g_tline[(4 * l42 + 1) * 64 + w2] = 0.5f * s2.y;
        g_tline[(4 * l42 + 2) * 64 + w2] = 0.5f * s2.z;
        g_tline[(4 * l42 + 3) * 64 + w2] = 0.5f * s2.w;
    }
}

// ================= K3: pre1 = b1 + W1a @ t_line =================
__global__ void k_pre1(const float* __restrict__ w1, const float* __restrict__ b1) {
    int f = blockIdx.x * 256 + threadIdx.x;   // f = b*4096 + o*64 + w
    int b = f >> 12, o = (f >> 6) & 63, w = f & 63;
    float s = __ldg(&b1[o]);
    #pragma unroll 8
    for (int c = 0; c < 64; c++)
        s = fmaf(__ldg(&w1[o * 128 + c]), g_tline[(b * 64 + c) * 64 + w], s);
    g_pre1[f] = s;
}

// ================= K4: per-voxel MLP + gated blend (fp16 mma) =================
// 1024 blocks x 512 thr; 256 voxels/block (two sequential 128-vox tiles).
// Epilogue v2: gates packed fp16 into the dead H16 region (GT16); blend reads
// x from the fp16 X16 tile (no img re-read) -> all-smem, coalesced epilogue.
// smem: X16@0 (17408) | H16/GT16@17408 (17408) | W1@34816 | W2@44032 |
//       PRE@53248 (17408) | TL@70656 (17408) | total 88064
#define SVB 272
#define SWB 144
__global__ __launch_bounds__(512, 2) void k_mlp(const float* __restrict__ img,
                                                const float* __restrict__ w1,
                                                const float* __restrict__ w2,
                                                const float* __restrict__ b2,
                                                float* __restrict__ out) {
    extern __shared__ char dsm[];
    const int X16 = 0, H16 = 17408, GT16 = 17408, W1O = 34816, W2O = 44032,
              PRE = 53248, TL = 70656;
    uint32_t sb = smem_u32(dsm);

    int t = threadIdx.x;
    int bb = blockIdx.x >> 9;
    int m0 = (blockIdx.x & 511) << 8;
    int w = t >> 5, lane = t & 31;
    int obase = (w & 3) * 16;
    int vwbase = (w >> 2) * 32;

    // ---- stage weights (fp16), pre1, tline (fp32) once per block ----
    for (int f = t; f < 2048; f += 512) {
        int o = f >> 5, c2 = f & 31;
        float2 a = *(const float2*)&w1[o * 128 + 64 + 2 * c2];
        *(uint32_t*)(dsm + W1O + o * SWB + c2 * 4) = pack_f16(a.x, a.y);
        float2 b = *(const float2*)&w2[o * 64 + 2 * c2];
        *(uint32_t*)(dsm + W2O + o * SWB + c2 * 4) = pack_f16(b.x, b.y);
    }
    for (int f = t; f < 1024; f += 512) {
        int o = f >> 4, w4 = f & 15;
        *(float4*)(dsm + PRE + o * 272 + w4 * 16) =
            *(const float4*)&g_pre1[bb * 4096 + o * 64 + w4 * 4];
        *(float4*)(dsm + TL + o * 272 + w4 * 16) =
            *(const float4*)&g_tline[bb * 4096 + o * 64 + w4 * 4];
    }

    int orow = obase + (lane >> 2);
    int vcol = 2 * (lane & 3);
    float bv0 = __ldg(&b2[orow]), bv1 = __ldg(&b2[orow + 8]);

    uint32_t aw_addr = (uint32_t)(obase + (lane & 15)) * SWB + (uint32_t)((lane >> 4) * 16);
    uint32_t bx_row = (uint32_t)(lane & 15) * SVB;
    uint32_t bx_col = (uint32_t)(vwbase * 2 + (lane >> 4) * 16);

    #pragma unroll 1
    for (int tile = 0; tile < 2; tile++) {
        int m0t = m0 + tile * 128;

        // ---- load x tile -> fp16 smem (wide) ----
        for (int f = t; f < 1024; f += 512) {
            int cc = f >> 3, v8 = f & 7;
            const float4* gp = (const float4*)(img + (size_t)(bb * 64 + cc) * M_DIM + m0t)
                             + v8 * 4;
            float4 x0 = gp[0], x1 = gp[1], x2 = gp[2], x3 = gp[3];
            *(uint4*)(dsm + X16 + cc * SVB + v8 * 32) =
                make_uint4(pack_f16(x0.x, x0.y), pack_f16(x0.z, x0.w),
                           pack_f16(x1.x, x1.y), pack_f16(x1.z, x1.w));
            *(uint4*)(dsm + X16 + cc * SVB + v8 * 32 + 16) =
                make_uint4(pack_f16(x2.x, x2.y), pack_f16(x2.z, x2.w),
                           pack_f16(x3.x, x3.y), pack_f16(x3.z, x3.w));
        }
        __syncthreads();   // X ready

        // ---- acc init from PRE smem ----
        float acc[4][4];
        #pragma unroll
        for (int j = 0; j < 4; j++) {
            int ws = (vwbase + 8 * j + vcol) & 63;
            float2 p0 = *(const float2*)(dsm + PRE + orow * 272 + ws * 4);
            float2 p1 = *(const float2*)(dsm + PRE + (orow + 8) * 272 + ws * 4);
            acc[j][0] = p0.x; acc[j][1] = p0.y;
            acc[j][2] = p1.x; acc[j][3] = p1.y;
        }

        // ---- layer 1: h = pre1 + W1b @ x ----
        #pragma unroll
        for (int k = 0; k < 4; k++) {
            uint32_t a[4];
            ldsm4(a, sb + W1O + aw_addr + k * 32u);
            #pragma unroll
            for (int q = 0; q < 2; q++) {
                uint32_t bx[4];
                ldsm4t(bx, sb + X16 + bx_row + (uint32_t)(16 * k) * SVB + bx_col + q * 32u);
                mma_f16(acc[2 * q],     a, bx[0], bx[1]);
                mma_f16(acc[2 * q + 1], a, bx[2], bx[3]);
            }
        }

        // ---- relu -> fp16 H smem ----
        #pragma unroll
        for (int j = 0; j < 4; j++) {
            int vox0 = vwbase + 8 * j + vcol;
            *(uint32_t*)(dsm + H16 + orow * SVB + vox0 * 2) =
                pack_f16(fmaxf(acc[j][0], 0.f), fmaxf(acc[j][1], 0.f));
            *(uint32_t*)(dsm + H16 + (orow + 8) * SVB + vox0 * 2) =
                pack_f16(fmaxf(acc[j][2], 0.f), fmaxf(acc[j][3], 0.f));
        }
        __syncthreads();

        // ---- layer 2: g = b2 + W2 @ H ----
        #pragma unroll
        for (int j = 0; j < 4; j++) {
            acc[j][0] = bv0; acc[j][1] = bv0;
            acc[j][2] = bv1; acc[j][3] = bv1;
        }
        #pragma unroll
        for (int k = 0; k < 4; k++) {
            uint32_t a[4];
            ldsm4(a, sb + W2O + aw_addr + k * 32u);
            #pragma unroll
            for (int q = 0; q < 2; q++) {
                uint32_t bh[4];
                ldsm4t(bh, sb + H16 + bx_row + (uint32_t)(16 * k) * SVB + bx_col + q * 32u);
                mma_f16(acc[2 * q],     a, bh[0], bh[1]);
                mma_f16(acc[2 * q + 1], a, bh[2], bh[3]);
            }
        }
        __syncthreads();   // all H reads done before GT16 overwrites that region

        // ---- gates -> fp16 GT16 [o][vox], pitch 272 (reuses H16 region) ----
        #pragma unroll
        for (int j = 0; j < 4; j++) {
            int vox0 = vwbase + 8 * j + vcol;
            *(uint32_t*)(dsm + GT16 + orow * SVB + vox0 * 2) =
                pack_f16(mufu_sigmoid(acc[j][0]), mufu_sigmoid(acc[j][1]));
            *(uint32_t*)(dsm + GT16 + (orow + 8) * SVB + vox0 * 2) =
                pack_f16(mufu_sigmoid(acc[j][2]), mufu_sigmoid(acc[j][3]));
        }
        __syncthreads();

        // ---- coalesced blend pass (all-smem): warp w owns rows 4w..4w+3 ----
        #pragma unroll
        for (int jr = 0; jr < 4; jr++) {
            int row = w * 4 + jr;
            size_t gidx = (size_t)(bb * 64 + row) * M_DIM + m0t + lane * 4;
            uint2 xu = *(const uint2*)(dsm + X16 + row * SVB + lane * 8);
            uint2 gu = *(const uint2*)(dsm + GT16 + row * SVB + lane * 8);
            float4 tv = *(const float4*)(dsm + TL + row * 272 + (lane & 15) * 16);
            float2 x0 = __half22float2(*(__half2*)&xu.x);
            float2 x1 = __half22float2(*(__half2*)&xu.y);
            float2 g0 = __half22float2(*(__half2*)&gu.x);
            float2 g1 = __half22float2(*(__half2*)&gu.y);
            float4 ov;
            ov.x = fmaf(g0.x, tv.x - x0.x, x0.x);
            ov.y = fmaf(g0.y, tv.y - x0.y, x0.y);
            ov.z = fmaf(g1.x, tv.z - x1.x, x1.x);
            ov.w = fmaf(g1.y, tv.w - x1.y, x1.y);
            *(float4*)(out + gidx) = ov;
        }
        __syncthreads();   // X16/GT16 reads done before next tile overwrites
    }
}

// ================= launch =================
extern "C" void kernel_launch(void* const* d_in, const int* in_sizes, int n_in,
                              void* d_out, int out_size) {
    const float* text = (const float*)d_in[0];
    const float* img  = (const float*)d_in[1];
    const float* w1   = (const float*)d_in[2];
    const float* b1   = (const float*)d_in[3];
    const float* w2   = (const float*)d_in[4];
    const float* b2   = (const float*)d_in[5];
    float* out = (float*)d_out;

    cudaFuncSetAttribute(k_fused, cudaFuncAttributeMaxDynamicSharedMemorySize, 209920);
    cudaFuncSetAttribute(k_mlp,   cudaFuncAttributeMaxDynamicSharedMemorySize, 88064);

    k_fused<<<128, 256, 209920>>>(img, text);
    k_redtl<<<128, 128>>>();
    k_pre1 <<<32, 256>>>(w1, b1);
    k_mlp  <<<1024, 512, 88064>>>(img, w1, w2, b2, out);
}

// round 15
// speedup vs baseline: 1.1706x; 1.1073x over previous
#include <cuda_runtime.h>
#include <cuda_bf16.h>
#include <cuda_fp16.h>
#include <math.h>
#include <stdint.h>

// ---------------- problem constants ----------------
#define L_DIM   128
#define N_DIM   256
#define M_DIM   131072
#define IMG_BSTRIDE 8388608   // 64*131072

// Only n in {4w+1, 4w+2} feed the output. sel s in [0,128): n = 4*(s>>1)+1+(s&1).

// ---------------- scratch (static device memory; no allocs) ----------------
__device__ float g_part[128 * 16384];          // alignedT partials [stripe][sel-n][l]
__device__ float g_tline[2 * 64 * 64];         // [b][c][w]  ([l][w], l = b*64+c)
__device__ float g_pre1[2 * 64 * 64];          // [b][o][w]

// ---------------- MUFU-based fast math ----------------
__device__ __forceinline__ float mufu_sigmoid(float x) {
    float e;
    asm("ex2.approx.f32 %0, %1;" : "=f"(e) : "f"(-1.4426950408889634f * x));
    float r;
    asm("rcp.approx.f32 %0, %1;" : "=f"(r) : "f"(1.0f + e));
    return r;
}
__device__ __forceinline__ float efun(float dot, float an, float bn) {
    float d2 = fmaxf(an + bn - 2.f * dot, 0.f);
    float c;
    asm("sqrt.approx.f32 %0, %1;" : "=f"(c) : "f"(d2));
    float e;
    asm("ex2.approx.f32 %0, %1;" : "=f"(e) : "f"(-0.14426950408889634f * c));
    return 1e-4f * e;
}

// ---------------- warp MMA helpers ----------------
__device__ __forceinline__ uint32_t smem_u32(const void* p) {
    uint32_t a;
    asm("{ .reg .u64 t; cvta.to.shared.u64 t, %1; cvt.u32.u64 %0, t; }" : "=r"(a) : "l"(p));
    return a;
}
__device__ __forceinline__ void ldsm4(uint32_t* r, uint32_t a) {
    asm volatile("ldmatrix.sync.aligned.m8n8.x4.shared.b16 {%0,%1,%2,%3}, [%4];"
                 : "=r"(r[0]), "=r"(r[1]), "=r"(r[2]), "=r"(r[3]) : "r"(a));
}
__device__ __forceinline__ void ldsm4t(uint32_t* r, uint32_t a) {
    asm volatile("ldmatrix.sync.aligned.m8n8.x4.trans.shared.b16 {%0,%1,%2,%3}, [%4];"
                 : "=r"(r[0]), "=r"(r[1]), "=r"(r[2]), "=r"(r[3]) : "r"(a));
}
__device__ __forceinline__ uint32_t movm(uint32_t a) {
    uint32_t d;
    asm volatile("movmatrix.sync.aligned.m8n8.trans.b16 %0, %1;" : "=r"(d) : "r"(a));
    return d;
}
__device__ __forceinline__ void mma_bf16(float* d, const uint32_t* a,
                                         uint32_t b0, uint32_t b1) {
    asm volatile("mma.sync.aligned.m16n8k16.row.col.f32.bf16.bf16.f32 "
                 "{%0,%1,%2,%3}, {%4,%5,%6,%7}, {%8,%9}, {%0,%1,%2,%3};"
                 : "+f"(d[0]), "+f"(d[1]), "+f"(d[2]), "+f"(d[3])
                 : "r"(a[0]), "r"(a[1]), "r"(a[2]), "r"(a[3]), "r"(b0), "r"(b1));
}
__device__ __forceinline__ void mma_f16(float* d, const uint32_t* a,
                                        uint32_t b0, uint32_t b1) {
    asm volatile("mma.sync.aligned.m16n8k16.row.col.f32.f16.f16.f32 "
                 "{%0,%1,%2,%3}, {%4,%5,%6,%7}, {%8,%9}, {%0,%1,%2,%3};"
                 : "+f"(d[0]), "+f"(d[1]), "+f"(d[2]), "+f"(d[3])
                 : "r"(a[0]), "r"(a[1]), "r"(a[2]), "r"(a[3]), "r"(b0), "r"(b1));
}
__device__ __forceinline__ uint32_t pack_bf16(float lo, float hi) {
    uint32_t r;
    asm("cvt.rn.bf16x2.f32 %0, %1, %2;" : "=r"(r) : "f"(hi), "f"(lo));
    return r;
}
__device__ __forceinline__ uint32_t pack_f16(float lo, float hi) {
    uint32_t r;
    asm("cvt.rn.f16x2.f32 %0, %1, %2;" : "=r"(r) : "f"(hi), "f"(lo));
    return r;
}
__device__ __forceinline__ void cp_async16(uint32_t daddr, const void* gptr) {
    asm volatile("cp.async.ca.shared.global [%0], [%1], 16;"
                 :: "r"(daddr), "l"(gptr) : "memory");
}
__device__ __forceinline__ float bf16_hl(uint32_t u, int hi) {
    uint16_t h = hi ? (uint16_t)(u >> 16) : (uint16_t)(u & 0xFFFF);
    return __bfloat162float(__ushort_as_bfloat16(h));
}

// ================= K1: fully-fused tensor-core pipeline (R11/R14 winner) ======
__global__ __launch_bounds__(256, 1) void k_fused(const float* __restrict__ img,
                                                  const float* __restrict__ text) {
    extern __shared__ char dsm[];
    const int TEXT = 0, STG0 = 34816, STG1 = 102400, IMGB = 169984,
              TMP = 204800, BN2 = 208896, AN2 = 209408;
    float* bn2s = (float*)(dsm + BN2);
    float* an2s = (float*)(dsm + AN2);

    int t = threadIdx.x, bid = blockIdx.x;
    int w = t >> 5, lane = t & 31;
    uint32_t sb = smem_u32(dsm);
    uint32_t sbi = sb + IMGB;

    for (int p = t; p < 8192; p += 256) {
        int s = p >> 6, c2 = p & 63;
        int n = 4 * (s >> 1) + 1 + (s & 1);
        *(uint32_t*)(dsm + TEXT + s * 272 + c2 * 4) =
            pack_bf16(__ldg(&text[(2 * c2) * 256 + n]),
                      __ldg(&text[(2 * c2 + 1) * 256 + n]));
    }

    {
        const char* gb = (const char*)(img + (size_t)bid * 1024);
        #pragma unroll
        for (int r = 0; r < 16; r++) {
            int f = t + 256 * r;
            int row = f >> 5, q = f & 31;
            cp_async16(sb + STG0 + (uint32_t)(row * 33 + q) * 16u,
                       gb + (size_t)row * 524288 + q * 16);
        }
        asm volatile("cp.async.commit_group;" ::: "memory");
    }
    __syncthreads();

    if (t < 128) {
        float s = 0.f;
        #pragma unroll 8
        for (int c2 = 0; c2 < 64; c2++) {
            uint32_t u = *(uint32_t*)(dsm + TEXT + t * 272 + c2 * 4);
            float v0 = bf16_hl(u, 0), v1 = bf16_hl(u, 1);
            s = fmaf(v0, v0, fmaf(v1, v1, s));
        }
        an2s[t] = s;
    }
    __syncthreads();

    uint32_t a_addr = (uint32_t)(w * 16 + (lane & 15)) * 272u
                    + (uint32_t)((lane >> 4) * 16);
    uint32_t atex[8][4];
    #pragma unroll
    for (int kk = 0; kk < 8; kk++)
        ldsm4(atex[kk], sb + TEXT + a_addr + kk * 32u);

    float acc2[16][4];
    #pragma unroll
    for (int lt = 0; lt < 16; lt++)
        #pragma unroll
        for (int r = 0; r < 4; r++) acc2[lt][r] = 0.f;

    float an2v0 = an2s[w * 16 + (lane >> 2)];
    float an2v1 = an2s[w * 16 + (lane >> 2) + 8];

    uint32_t b_row = (uint32_t)(lane & 15) * 272u;
    uint32_t b_colbase = (uint32_t)((lane >> 4) * 16);

    int c4 = t & 31;
    int rp = t >> 5;

    #pragma unroll 1
    for (int c = 0; c < 8; c++) {
        if (c < 7) {
            uint32_t dst = sb + (((c + 1) & 1) ? STG1 : STG0);
            const char* gb = (const char*)(img + (size_t)bid * 1024 + (c + 1) * 128);
            #pragma unroll
            for (int r = 0; r < 16; r++) {
                int f = t + 256 * r;
                int row = f >> 5, q = f & 31;
                cp_async16(dst + (uint32_t)(row * 33 + q) * 16u,
                           gb + (size_t)row * 524288 + q * 16);
            }
            asm volatile("cp.async.commit_group;" ::: "memory");
            asm volatile("cp.async.wait_group 1;" ::: "memory");
        } else {
            asm volatile("cp.async.wait_group 0;" ::: "memory");
        }
        __syncthreads();

        {
            const char* stg = dsm + ((c & 1) ? STG1 : STG0);
            float s0 = 0.f, s1 = 0.f, s2 = 0.f, s3 = 0.f;
            #pragma unroll 8
            for (int i = 0; i < 16; i++) {
                int row = rp + 8 * i;
                float4 v = *(const float4*)(stg + row * 528 + c4 * 16);
                s0 = fmaf(v.x, v.x, s0);
                s1 = fmaf(v.y, v.y, s1);
                s2 = fmaf(v.z, v.z, s2);
                s3 = fmaf(v.w, v.w, s3);
                *(uint2*)(dsm + IMGB + row * 272 + c4 * 8) =
                    make_uint2(pack_bf16(v.x, v.y), pack_bf16(v.z, v.w));
            }
            ((float4*)(dsm + TMP))[t] = make_float4(s0, s1, s2, s3);
        }
        __syncthreads();
        if (t < 128) {
            float v = 0.f;
            #pragma unroll
            for (int q = 0; q < 8; q++)
                v += ((const float*)(dsm + TMP))[(q * 32 + (t >> 2)) * 4 + (t & 3)];
            bn2s[t] = v;
        }
        __syncthreads();

        #pragma unroll 1
        for (int s = 0; s < 8; s++) {
            uint32_t scol = (uint32_t)(s * 32) + b_colbase;

            float c1[2][4];
            #pragma unroll
            for (int j = 0; j < 2; j++)
                #pragma unroll
                for (int r = 0; r < 4; r++) c1[j][r] = 0.f;

            uint32_t bsave[8][4];
            #pragma unroll
            for (int kk = 0; kk < 8; kk++) {
                ldsm4t(bsave[kk], sbi + b_row + (uint32_t)(kk * 16) * 272u + scol);
                mma_bf16(c1[0], atex[kk], bsave[kk][0], bsave[kk][1]);
                mma_bf16(c1[1], atex[kk], bsave[kk][2], bsave[kk][3]);
            }

            uint32_t a2[4];
            #pragma unroll
            for (int j = 0; j < 2; j++) {
                float2 bn = *(float2*)&bn2s[s * 16 + j * 8 + 2 * (lane & 3)];
                float e0 = efun(c1[j][0], an2v0, bn.x);
                float e1 = efun(c1[j][1], an2v0, bn.y);
                float e2 = efun(c1[j][2], an2v1, bn.x);
                float e3 = efun(c1[j][3], an2v1, bn.y);
                a2[2 * j]     = pack_bf16(e0, e1);
                a2[2 * j + 1] = pack_bf16(e2, e3);
            }

            #pragma unroll
            for (int lb = 0; lb < 8; lb++) {
                uint32_t m0r = movm(bsave[lb][0]);
                uint32_t m1r = movm(bsave[lb][1]);
                uint32_t m2r = movm(bsave[lb][2]);
                uint32_t m3r = movm(bsave[lb][3]);
                mma_bf16(acc2[2 * lb],     a2, m0r, m2r);
                mma_bf16(acc2[2 * lb + 1], a2, m1r, m3r);
            }
        }
        __syncthreads();
    }

    int nbase = w * 16 + (lane >> 2);
    #pragma unroll
    for (int lt = 0; lt < 16; lt++) {
        int l = lt * 8 + 2 * (lane & 3);
        size_t base = (size_t)bid * 16384 + (size_t)nbase * 128 + l;
        *(float2*)&g_part[base] = make_float2(acc2[lt][0], acc2[lt][1]);
        *(float2*)&g_part[base + 8 * 128] = make_float2(acc2[lt][2], acc2[lt][3]);
    }
}

// ================= K2: split-K reduce partials + interp -> t_line =============
__global__ void k_redtl() {
    __shared__ float4 red[128];
    int t = threadIdx.x, B = blockIdx.x;
    int out = B * 16 + (t & 15);
    int split = t >> 4;
    int w = out >> 5, l4 = out & 31;
    const float4* p4 = (const float4*)g_part;
    float4 s = make_float4(0.f, 0.f, 0.f, 0.f);
    #pragma unroll 4
    for (int st = split * 16; st < split * 16 + 16; st++) {
        float4 a = p4[(size_t)st * 4096 + (2 * w) * 32 + l4];
        float4 b = p4[(size_t)st * 4096 + (2 * w + 1) * 32 + l4];
        s.x += a.x + b.x; s.y += a.y + b.y;
        s.z += a.z + b.z; s.w += a.w + b.w;
    }
    red[t] = s;
    __syncthreads();
    if (t < 16) {
        float4 s2 = red[t];
        #pragma unroll
        for (int q = 1; q < 8; q++) {
            float4 r = red[t + 16 * q];
            s2.x += r.x; s2.y += r.y; s2.z += r.z; s2.w += r.w;
        }
        int o2 = B * 16 + t;
        int w2 = o2 >> 5, l42 = o2 & 31;
        g_tline[(4 * l42 + 0) * 64 + w2] = 0.5f * s2.x;
        g_tline[(4 * l42 + 1) * 64 + w2] = 0.5f * s2.y;
        g_tline[(4 * l42 + 2) * 64 + w2] = 0.5f * s2.z;
        g_tline[(4 * l42 + 3) * 64 + w2] = 0.5f * s2.w;
    }
}

// ================= K3: pre1 = b1 + W1a @ t_line =================
__global__ void k_pre1(const float* __restrict__ w1, const float* __restrict__ b1) {
    int f = blockIdx.x * 256 + threadIdx.x;
    int b = f >> 12, o = (f >> 6) & 63, w = f & 63;
    float s = __ldg(&b1[o]);
    #pragma unroll 8
    for (int c = 0; c < 64; c++)
        s = fmaf(__ldg(&w1[o * 128 + c]), g_tline[(b * 64 + c) * 64 + w], s);
    g_pre1[f] = s;
}

// ================= K4: per-voxel MLP + gated blend (register-resident H) ======
// 2048 blocks x 256 thr, 3 CTA/SM; 128 vox/block, ONE pass.
// Each warp: 16 vox (vwbase = w*16), ALL 64 o (4 m-tiles x 2 n-tiles).
// Layer2 B-operands derived IN REGISTERS from layer1 accumulators via
// pack_f16 + movmatrix (no H smem round-trip, no relu STS, no layer2 ldsm4t).
// smem: X16@0 (64x272) | GT16@17408 (64x272) | W1@34816 (64x144) |
//       W2@44032 | PRE16@53248 (64x136) | TL16@61952 (64x136) | total 70656
#define SVB2 272
#define PRP  136
__global__ __launch_bounds__(256, 3) void k_mlp(const float* __restrict__ img,
                                                const float* __restrict__ w1,
                                                const float* __restrict__ w2,
                                                const float* __restrict__ b2,
                                                float* __restrict__ out) {
    extern __shared__ char dsm[];
    const int X16 = 0, GT16 = 17408, W1O = 34816, W2O = 44032,
              PRE = 53248, TL = 61952;
    uint32_t sb = smem_u32(dsm);

    int t = threadIdx.x;
    int bb = blockIdx.x >> 10;
    int m0 = (blockIdx.x & 1023) << 7;
    int w = t >> 5, lane = t & 31;
    int vwbase = w * 16;
    int r = lane >> 2;
    int vcol = 2 * (lane & 3);

    // ---- stage weights fp16 ----
    for (int f = t; f < 2048; f += 256) {
        int o = f >> 5, c2 = f & 31;
        float2 a = *(const float2*)&w1[o * 128 + 64 + 2 * c2];
        *(uint32_t*)(dsm + W1O + o * 144 + c2 * 4) = pack_f16(a.x, a.y);
        float2 b = *(const float2*)&w2[o * 64 + 2 * c2];
        *(uint32_t*)(dsm + W2O + o * 144 + c2 * 4) = pack_f16(b.x, b.y);
    }
    // ---- stage pre1 / tline fp16 ----
    for (int f = t; f < 1024; f += 256) {
        int o = f >> 4, w4 = f & 15;
        float4 p = *(const float4*)&g_pre1[bb * 4096 + o * 64 + w4 * 4];
        *(uint2*)(dsm + PRE + o * PRP + w4 * 8) =
            make_uint2(pack_f16(p.x, p.y), pack_f16(p.z, p.w));
        float4 q = *(const float4*)&g_tline[bb * 4096 + o * 64 + w4 * 4];
        *(uint2*)(dsm + TL + o * PRP + w4 * 8) =
            make_uint2(pack_f16(q.x, q.y), pack_f16(q.z, q.w));
    }
    // ---- stage x fp16 [64 c][128 vox] ----
    for (int f = t; f < 1024; f += 256) {
        int cc = f >> 4, v = f & 15;
        const float4* gp = (const float4*)(img + (size_t)(bb * 64 + cc) * M_DIM + m0)
                         + v * 2;
        float4 x0 = gp[0], x1 = gp[1];
        *(uint4*)(dsm + X16 + cc * SVB2 + v * 16) =
            make_uint4(pack_f16(x0.x, x0.y), pack_f16(x0.z, x0.w),
                       pack_f16(x1.x, x1.y), pack_f16(x1.z, x1.w));
    }
    __syncthreads();

    // ---- acc init from PRE16 ----
    float acc[4][2][4];
    #pragma unroll
    for (int mt = 0; mt < 4; mt++)
        #pragma unroll
        for (int nt = 0; nt < 2; nt++) {
            int ws = (vwbase + 8 * nt + vcol) & 63;
            uint32_t p0 = *(const uint32_t*)(dsm + PRE + (16 * mt + r) * PRP + ws * 2);
            uint32_t p1 = *(const uint32_t*)(dsm + PRE + (16 * mt + r + 8) * PRP + ws * 2);
            float2 f0 = __half22float2(*(__half2*)&p0);
            float2 f1 = __half22float2(*(__half2*)&p1);
            acc[mt][nt][0] = f0.x; acc[mt][nt][1] = f0.y;
            acc[mt][nt][2] = f1.x; acc[mt][nt][3] = f1.y;
        }

    uint32_t aw_base = (uint32_t)(lane & 15) * 144u + (uint32_t)((lane >> 4) * 16);
    uint32_t bx_addr = (uint32_t)(lane & 15) * SVB2
                     + (uint32_t)(vwbase * 2 + (lane >> 4) * 16);

    // ---- layer 1: h = pre1 + W1b @ x ----
    #pragma unroll
    for (int k = 0; k < 4; k++) {
        uint32_t bx[4];
        ldsm4t(bx, sb + X16 + bx_addr + (uint32_t)(16 * k) * SVB2);
        #pragma unroll
        for (int mt = 0; mt < 4; mt++) {
            uint32_t a[4];
            ldsm4(a, sb + W1O + (uint32_t)(mt * 16) * 144u + aw_base + k * 32u);
            mma_f16(acc[mt][0], a, bx[0], bx[1]);
            mma_f16(acc[mt][1], a, bx[2], bx[3]);
        }
    }

    // ---- relu -> layer2 B-fragments in registers (pack + movmatrix) ----
    uint32_t bfr[4][2][2];
    #pragma unroll
    for (int k = 0; k < 4; k++)
        #pragma unroll
        for (int nt = 0; nt < 2; nt++) {
            bfr[k][nt][0] = movm(pack_f16(fmaxf(acc[k][nt][0], 0.f),
                                          fmaxf(acc[k][nt][1], 0.f)));
            bfr[k][nt][1] = movm(pack_f16(fmaxf(acc[k][nt][2], 0.f),
                                          fmaxf(acc[k][nt][3], 0.f)));
        }

    // ---- layer 2: g = b2 + W2 @ H (B from registers) ----
    #pragma unroll
    for (int mt = 0; mt < 4; mt++) {
        float bva = __ldg(&b2[16 * mt + r]);
        float bvb = __ldg(&b2[16 * mt + r + 8]);
        #pragma unroll
        for (int nt = 0; nt < 2; nt++) {
            acc[mt][nt][0] = bva; acc[mt][nt][1] = bva;
            acc[mt][nt][2] = bvb; acc[mt][nt][3] = bvb;
        }
    }
    #pragma unroll
    for (int k = 0; k < 4; k++) {
        #pragma unroll
        for (int mt = 0; mt < 4; mt++) {
            uint32_t a[4];
            ldsm4(a, sb + W2O + (uint32_t)(mt * 16) * 144u + aw_base + k * 32u);
            mma_f16(acc[mt][0], a, bfr[k][0][0], bfr[k][0][1]);
            mma_f16(acc[mt][1], a, bfr[k][1][0], bfr[k][1][1]);
        }
    }

    // ---- gates -> fp16 GT16 [o][vox] (conflict-free STS.32) ----
    #pragma unroll
    for (int mt = 0; mt < 4; mt++)
        #pragma unroll
        for (int nt = 0; nt < 2; nt++) {
            int vox0 = vwbase + 8 * nt + vcol;
            *(uint32_t*)(dsm + GT16 + (16 * mt + r) * SVB2 + vox0 * 2) =
                pack_f16(mufu_sigmoid(acc[mt][nt][0]), mufu_sigmoid(acc[mt][nt][1]));
            *(uint32_t*)(dsm + GT16 + (16 * mt + r + 8) * SVB2 + vox0 * 2) =
                pack_f16(mufu_sigmoid(acc[mt][nt][2]), mufu_sigmoid(acc[mt][nt][3]));
        }
    __syncthreads();

    // ---- coalesced blend: warp w owns rows 8w..8w+7; vox = lane*4 ----
    #pragma unroll
    for (int jr = 0; jr < 8; jr++) {
        int row = w * 8 + jr;
        size_t gidx = (size_t)(bb * 64 + row) * M_DIM + m0 + lane * 4;
        uint2 xu = *(const uint2*)(dsm + X16 + row * SVB2 + lane * 8);
        uint2 gu = *(const uint2*)(dsm + GT16 + row * SVB2 + lane * 8);
        uint2 tu = *(const uint2*)(dsm + TL + row * PRP + (lane & 15) * 8);
        float2 x0 = __half22float2(*(__half2*)&xu.x);
        float2 x1 = __half22float2(*(__half2*)&xu.y);
        float2 g0 = __half22float2(*(__half2*)&gu.x);
        float2 g1 = __half22float2(*(__half2*)&gu.y);
        float2 t0 = __half22float2(*(__half2*)&tu.x);
        float2 t1 = __half22float2(*(__half2*)&tu.y);
        float4 ov;
        ov.x = fmaf(g0.x, t0.x - x0.x, x0.x);
        ov.y = fmaf(g0.y, t0.y - x0.y, x0.y);
        ov.z = fmaf(g1.x, t1.x - x1.x, x1.x);
        ov.w = fmaf(g1.y, t1.y - x1.y, x1.y);
        *(float4*)(out + gidx) = ov;
    }
}

// ================= launch =================
extern "C" void kernel_launch(void* const* d_in, const int* in_sizes, int n_in,
                              void* d_out, int out_size) {
    const float* text = (const float*)d_in[0];
    const float* img  = (const float*)d_in[1];
    const float* w1   = (const float*)d_in[2];
    const float* b1   = (const float*)d_in[3];
    const float* w2   = (const float*)d_in[4];
    const float* b2   = (const float*)d_in[5];
    float* out = (float*)d_out;

    cudaFuncSetAttribute(k_fused, cudaFuncAttributeMaxDynamicSharedMemorySize, 209920);
    cudaFuncSetAttribute(k_mlp,   cudaFuncAttributeMaxDynamicSharedMemorySize, 70656);

    k_fused<<<128, 256, 209920>>>(img, text);
    k_redtl<<<128, 128>>>();
    k_pre1 <<<32, 256>>>(w1, b1);
    k_mlp  <<<2048, 256, 70656>>>(img, w1, w2, b2, out);
}

// round 16
// speedup vs baseline: 1.2397x; 1.0590x over previous
#include <cuda_runtime.h>
#include <cuda_bf16.h>
#include <cuda_fp16.h>
#include <math.h>
#include <stdint.h>

// ---------------- problem constants ----------------
#define L_DIM   128
#define N_DIM   256
#define M_DIM   131072
#define IMG_BSTRIDE 8388608   // 64*131072

// Only n in {4w+1, 4w+2} feed the output. sel s in [0,128): n = 4*(s>>1)+1+(s&1).

// ---------------- scratch (static device memory; no allocs) ----------------
__device__ float g_part[128 * 16384];          // alignedT partials [stripe][sel-n][l]
__device__ float g_tline[2 * 64 * 64];         // [b][c][w]  ([l][w], l = b*64+c)
__device__ float g_pre1[2 * 64 * 64];          // [b][o][w]

// ---------------- MUFU-based fast math ----------------
__device__ __forceinline__ float mufu_sigmoid(float x) {
    float e;
    asm("ex2.approx.f32 %0, %1;" : "=f"(e) : "f"(-1.4426950408889634f * x));
    float r;
    asm("rcp.approx.f32 %0, %1;" : "=f"(r) : "f"(1.0f + e));
    return r;
}
__device__ __forceinline__ float efun(float dot, float an, float bn) {
    float d2 = fmaxf(an + bn - 2.f * dot, 0.f);
    float c;
    asm("sqrt.approx.f32 %0, %1;" : "=f"(c) : "f"(d2));
    float e;
    asm("ex2.approx.f32 %0, %1;" : "=f"(e) : "f"(-0.14426950408889634f * c));
    return 1e-4f * e;
}

// ---------------- warp MMA helpers ----------------
__device__ __forceinline__ uint32_t smem_u32(const void* p) {
    uint32_t a;
    asm("{ .reg .u64 t; cvta.to.shared.u64 t, %1; cvt.u32.u64 %0, t; }" : "=r"(a) : "l"(p));
    return a;
}
__device__ __forceinline__ void ldsm4(uint32_t* r, uint32_t a) {
    asm volatile("ldmatrix.sync.aligned.m8n8.x4.shared.b16 {%0,%1,%2,%3}, [%4];"
                 : "=r"(r[0]), "=r"(r[1]), "=r"(r[2]), "=r"(r[3]) : "r"(a));
}
__device__ __forceinline__ void ldsm4t(uint32_t* r, uint32_t a) {
    asm volatile("ldmatrix.sync.aligned.m8n8.x4.trans.shared.b16 {%0,%1,%2,%3}, [%4];"
                 : "=r"(r[0]), "=r"(r[1]), "=r"(r[2]), "=r"(r[3]) : "r"(a));
}
__device__ __forceinline__ uint32_t movm(uint32_t a) {
    uint32_t d;
    asm volatile("movmatrix.sync.aligned.m8n8.trans.b16 %0, %1;" : "=r"(d) : "r"(a));
    return d;
}
__device__ __forceinline__ void mma_bf16(float* d, const uint32_t* a,
                                         uint32_t b0, uint32_t b1) {
    asm volatile("mma.sync.aligned.m16n8k16.row.col.f32.bf16.bf16.f32 "
                 "{%0,%1,%2,%3}, {%4,%5,%6,%7}, {%8,%9}, {%0,%1,%2,%3};"
                 : "+f"(d[0]), "+f"(d[1]), "+f"(d[2]), "+f"(d[3])
                 : "r"(a[0]), "r"(a[1]), "r"(a[2]), "r"(a[3]), "r"(b0), "r"(b1));
}
__device__ __forceinline__ void mma_f16(float* d, const uint32_t* a,
                                        uint32_t b0, uint32_t b1) {
    asm volatile("mma.sync.aligned.m16n8k16.row.col.f32.f16.f16.f32 "
                 "{%0,%1,%2,%3}, {%4,%5,%6,%7}, {%8,%9}, {%0,%1,%2,%3};"
                 : "+f"(d[0]), "+f"(d[1]), "+f"(d[2]), "+f"(d[3])
                 : "r"(a[0]), "r"(a[1]), "r"(a[2]), "r"(a[3]), "r"(b0), "r"(b1));
}
__device__ __forceinline__ uint32_t pack_bf16(float lo, float hi) {
    uint32_t r;
    asm("cvt.rn.bf16x2.f32 %0, %1, %2;" : "=r"(r) : "f"(hi), "f"(lo));
    return r;
}
__device__ __forceinline__ uint32_t pack_f16(float lo, float hi) {
    uint32_t r;
    asm("cvt.rn.f16x2.f32 %0, %1, %2;" : "=r"(r) : "f"(hi), "f"(lo));
    return r;
}
__device__ __forceinline__ void cp_async16(uint32_t daddr, const void* gptr) {
    asm volatile("cp.async.ca.shared.global [%0], [%1], 16;"
                 :: "r"(daddr), "l"(gptr) : "memory");
}
__device__ __forceinline__ float bf16_hl(uint32_t u, int hi) {
    uint16_t h = hi ? (uint16_t)(u >> 16) : (uint16_t)(u & 0xFFFF);
    return __bfloat162float(__ushort_as_bfloat16(h));
}

// ================= K1: fused pipeline, convert/mma overlapped =================
// 128 CTAs x 256 thr, 1/SM. CTA = m-stripe of 1024 (8 chunks of 128 m).
// Double-buffered IMGB + bn2: iter c converts chunk c+1 then (no barrier)
// runs GEMM/E/GEMM on chunk c, so warps drain from convert into mma.
// smem: TEXT@0 34816 | STG@34816 67584 | IMGB0@102400 | IMGB1@137216 |
//   TMP@172032 4096 | BN2@176128 1024 (x2) | AN2@177152 512 | total 177664
__global__ __launch_bounds__(256, 1) void k_fused(const float* __restrict__ img,
                                                  const float* __restrict__ text) {
    extern __shared__ char dsm[];
    const int TEXT = 0, STG = 34816, IMGB0 = 102400, IMGB1 = 137216,
              TMP = 172032, BN2 = 176128, AN2 = 177152;
    float* bn2s = (float*)(dsm + BN2);   // [2][128]
    float* an2s = (float*)(dsm + AN2);

    int t = threadIdx.x, bid = blockIdx.x;
    int w = t >> 5, lane = t & 31;
    uint32_t sb = smem_u32(dsm);

    int c4 = t & 31;
    int rp = t >> 5;

    // ---- build text tile + issue chunk 0 ----
    for (int p = t; p < 8192; p += 256) {
        int s = p >> 6, c2 = p & 63;
        int n = 4 * (s >> 1) + 1 + (s & 1);
        *(uint32_t*)(dsm + TEXT + s * 272 + c2 * 4) =
            pack_bf16(__ldg(&text[(2 * c2) * 256 + n]),
                      __ldg(&text[(2 * c2 + 1) * 256 + n]));
    }
    {
        const char* gb = (const char*)(img + (size_t)bid * 1024);
        #pragma unroll
        for (int r = 0; r < 16; r++) {
            int f = t + 256 * r;
            int row = f >> 5, q = f & 31;
            cp_async16(sb + STG + (uint32_t)(row * 33 + q) * 16u,
                       gb + (size_t)row * 524288 + q * 16);
        }
        asm volatile("cp.async.commit_group;" ::: "memory");
    }
    __syncthreads();   // TEXT ready

    if (t < 128) {
        float s = 0.f;
        #pragma unroll 8
        for (int c2 = 0; c2 < 64; c2++) {
            uint32_t u = *(uint32_t*)(dsm + TEXT + t * 272 + c2 * 4);
            float v0 = bf16_hl(u, 0), v1 = bf16_hl(u, 1);
            s = fmaf(v0, v0, fmaf(v1, v1, s));
        }
        an2s[t] = s;
    }
    __syncthreads();   // an2 ready

    uint32_t a_addr = (uint32_t)(w * 16 + (lane & 15)) * 272u
                    + (uint32_t)((lane >> 4) * 16);
    uint32_t atex[8][4];
    #pragma unroll
    for (int kk = 0; kk < 8; kk++)
        ldsm4(atex[kk], sb + TEXT + a_addr + kk * 32u);

    float an2v0 = an2s[w * 16 + (lane >> 2)];
    float an2v1 = an2s[w * 16 + (lane >> 2) + 8];

    float acc2[16][4];
    #pragma unroll
    for (int lt = 0; lt < 16; lt++)
        #pragma unroll
        for (int r = 0; r < 4; r++) acc2[lt][r] = 0.f;

    uint32_t b_row = (uint32_t)(lane & 15) * 272u;
    uint32_t b_colbase = (uint32_t)((lane >> 4) * 16);

    // ---- prologue: convert chunk 0 -> IMGB0 / bn2[0]; issue chunk 1 ----
    asm volatile("cp.async.wait_group 0;" ::: "memory");
    __syncthreads();
    {
        const char* stg = dsm + STG;
        float s0 = 0.f, s1 = 0.f, s2 = 0.f, s3 = 0.f;
        #pragma unroll 8
        for (int i = 0; i < 16; i++) {
            int row = rp + 8 * i;
            float4 v = *(const float4*)(stg + row * 528 + c4 * 16);
            s0 = fmaf(v.x, v.x, s0);
            s1 = fmaf(v.y, v.y, s1);
            s2 = fmaf(v.z, v.z, s2);
            s3 = fmaf(v.w, v.w, s3);
            *(uint2*)(dsm + IMGB0 + row * 272 + c4 * 8) =
                make_uint2(pack_bf16(v.x, v.y), pack_bf16(v.z, v.w));
        }
        ((float4*)(dsm + TMP))[t] = make_float4(s0, s1, s2, s3);
    }
    __syncthreads();
    if (t < 128) {
        float v = 0.f;
        #pragma unroll
        for (int q = 0; q < 8; q++)
            v += ((const float*)(dsm + TMP))[(q * 32 + (t >> 2)) * 4 + (t & 3)];
        bn2s[t] = v;
    }
    {
        const char* gb = (const char*)(img + (size_t)bid * 1024 + 128);
        #pragma unroll
        for (int r = 0; r < 16; r++) {
            int f = t + 256 * r;
            int row = f >> 5, q = f & 31;
            cp_async16(sb + STG + (uint32_t)(row * 33 + q) * 16u,
                       gb + (size_t)row * 524288 + q * 16);
        }
        asm volatile("cp.async.commit_group;" ::: "memory");
    }

    // ---- main loop ----
    #pragma unroll 1
    for (int c = 0; c < 8; c++) {
        if (c < 7) {
            asm volatile("cp.async.wait_group 0;" ::: "memory");
            __syncthreads();   // STG(c+1) visible; protects IMGB[(c+1)&1] (mma c-1 done)
            // convert chunk c+1 -> IMGB[(c+1)&1]
            {
                const char* stg = dsm + STG;
                uint32_t ib = ((c + 1) & 1) ? IMGB1 : IMGB0;
                float s0 = 0.f, s1 = 0.f, s2 = 0.f, s3 = 0.f;
                #pragma unroll 8
                for (int i = 0; i < 16; i++) {
                    int row = rp + 8 * i;
                    float4 v = *(const float4*)(stg + row * 528 + c4 * 16);
                    s0 = fmaf(v.x, v.x, s0);
                    s1 = fmaf(v.y, v.y, s1);
                    s2 = fmaf(v.z, v.z, s2);
                    s3 = fmaf(v.w, v.w, s3);
                    *(uint2*)(dsm + ib + row * 272 + c4 * 8) =
                        make_uint2(pack_bf16(v.x, v.y), pack_bf16(v.z, v.w));
                }
                ((float4*)(dsm + TMP))[t] = make_float4(s0, s1, s2, s3);
            }
            __syncthreads();   // TMP ready; STG consumed; bn2[c&1] (prev) visible
            if (t < 128) {
                float v = 0.f;
                #pragma unroll
                for (int q = 0; q < 8; q++)
                    v += ((const float*)(dsm + TMP))[(q * 32 + (t >> 2)) * 4 + (t & 3)];
                bn2s[((c + 1) & 1) * 128 + t] = v;
            }
            if (c < 6) {
                const char* gb = (const char*)(img + (size_t)bid * 1024 + (c + 2) * 128);
                #pragma unroll
                for (int r = 0; r < 16; r++) {
                    int f = t + 256 * r;
                    int row = f >> 5, q = f & 31;
                    cp_async16(sb + STG + (uint32_t)(row * 33 + q) * 16u,
                               gb + (size_t)row * 524288 + q * 16);
                }
                asm volatile("cp.async.commit_group;" ::: "memory");
            }
        } else {
            __syncthreads();   // orders bn2[1] written in iter 6 before mma(7)
        }

        // ---- mma phase on chunk c (no barrier after convert -> overlap) ----
        uint32_t sbi = sb + ((c & 1) ? IMGB1 : IMGB0);
        const float* bnp = bn2s + (c & 1) * 128;

        #pragma unroll 1
        for (int s = 0; s < 8; s++) {
            uint32_t scol = (uint32_t)(s * 32) + b_colbase;

            float c1[2][4];
            #pragma unroll
            for (int j = 0; j < 2; j++)
                #pragma unroll
                for (int r = 0; r < 4; r++) c1[j][r] = 0.f;

            uint32_t bsave[8][4];
            #pragma unroll
            for (int kk = 0; kk < 8; kk++) {
                ldsm4t(bsave[kk], sbi + b_row + (uint32_t)(kk * 16) * 272u + scol);
                mma_bf16(c1[0], atex[kk], bsave[kk][0], bsave[kk][1]);
                mma_bf16(c1[1], atex[kk], bsave[kk][2], bsave[kk][3]);
            }

            uint32_t a2[4];
            #pragma unroll
            for (int j = 0; j < 2; j++) {
                float2 bn = *(float2*)&bnp[s * 16 + j * 8 + 2 * (lane & 3)];
                float e0 = efun(c1[j][0], an2v0, bn.x);
                float e1 = efun(c1[j][1], an2v0, bn.y);
                float e2 = efun(c1[j][2], an2v1, bn.x);
                float e3 = efun(c1[j][3], an2v1, bn.y);
                a2[2 * j]     = pack_bf16(e0, e1);
                a2[2 * j + 1] = pack_bf16(e2, e3);
            }

            #pragma unroll
            for (int lb = 0; lb < 8; lb++) {
                uint32_t m0r = movm(bsave[lb][0]);
                uint32_t m1r = movm(bsave[lb][1]);
                uint32_t m2r = movm(bsave[lb][2]);
                uint32_t m3r = movm(bsave[lb][3]);
                mma_bf16(acc2[2 * lb],     a2, m0r, m2r);
                mma_bf16(acc2[2 * lb + 1], a2, m1r, m3r);
            }
        }
    }

    // store partials: g_part[bid][sel-n][l]
    int nbase = w * 16 + (lane >> 2);
    #pragma unroll
    for (int lt = 0; lt < 16; lt++) {
        int l = lt * 8 + 2 * (lane & 3);
        size_t base = (size_t)bid * 16384 + (size_t)nbase * 128 + l;
        *(float2*)&g_part[base] = make_float2(acc2[lt][0], acc2[lt][1]);
        *(float2*)&g_part[base + 8 * 128] = make_float2(acc2[lt][2], acc2[lt][3]);
    }
}

// ================= K2: split-K reduce partials + interp -> t_line =============
__global__ void k_redtl() {
    __shared__ float4 red[128];
    int t = threadIdx.x, B = blockIdx.x;
    int out = B * 16 + (t & 15);
    int split = t >> 4;
    int w = out >> 5, l4 = out & 31;
    const float4* p4 = (const float4*)g_part;
    float4 s = make_float4(0.f, 0.f, 0.f, 0.f);
    #pragma unroll 4
    for (int st = split * 16; st < split * 16 + 16; st++) {
        float4 a = p4[(size_t)st * 4096 + (2 * w) * 32 + l4];
        float4 b = p4[(size_t)st * 4096 + (2 * w + 1) * 32 + l4];
        s.x += a.x + b.x; s.y += a.y + b.y;
        s.z += a.z + b.z; s.w += a.w + b.w;
    }
    red[t] = s;
    __syncthreads();
    if (t < 16) {
        float4 s2 = red[t];
        #pragma unroll
        for (int q = 1; q < 8; q++) {
            float4 r = red[t + 16 * q];
            s2.x += r.x; s2.y += r.y; s2.z += r.z; s2.w += r.w;
        }
        int o2 = B * 16 + t;
        int w2 = o2 >> 5, l42 = o2 & 31;
        g_tline[(4 * l42 + 0) * 64 + w2] = 0.5f * s2.x;
        g_tline[(4 * l42 + 1) * 64 + w2] = 0.5f * s2.y;
        g_tline[(4 * l42 + 2) * 64 + w2] = 0.5f * s2.z;
        g_tline[(4 * l42 + 3) * 64 + w2] = 0.5f * s2.w;
    }
}

// ================= K3: pre1 = b1 + W1a @ t_line =================
__global__ void k_pre1(const float* __restrict__ w1, const float* __restrict__ b1) {
    int f = blockIdx.x * 256 + threadIdx.x;
    int b = f >> 12, o = (f >> 6) & 63, w = f & 63;
    float s = __ldg(&b1[o]);
    #pragma unroll 8
    for (int c = 0; c < 64; c++)
        s = fmaf(__ldg(&w1[o * 128 + c]), g_tline[(b * 64 + c) * 64 + w], s);
    g_pre1[f] = s;
}

// ================= K4: MLP, register-resident H, 2 tiles per block ============
// 1024 blocks x 256 thr, 3 CTA/SM; 256 vox/block as two 128-vox tiles;
// weights/pre1/tline staged once per block.
#define SVB2 272
#define PRP  136
__global__ __launch_bounds__(256, 3) void k_mlp(const float* __restrict__ img,
                                                const float* __restrict__ w1,
                                                const float* __restrict__ w2,
                                                const float* __restrict__ b2,
                                                float* __restrict__ out) {
    extern __shared__ char dsm[];
    const int X16 = 0, GT16 = 17408, W1O = 34816, W2O = 44032,
              PRE = 53248, TL = 61952;
    uint32_t sb = smem_u32(dsm);

    int t = threadIdx.x;
    int bb = blockIdx.x >> 9;
    int m0 = (blockIdx.x & 511) << 8;
    int w = t >> 5, lane = t & 31;
    int vwbase = w * 16;
    int r = lane >> 2;
    int vcol = 2 * (lane & 3);

    // ---- stage weights fp16 (once) ----
    for (int f = t; f < 2048; f += 256) {
        int o = f >> 5, c2 = f & 31;
        float2 a = *(const float2*)&w1[o * 128 + 64 + 2 * c2];
        *(uint32_t*)(dsm + W1O + o * 144 + c2 * 4) = pack_f16(a.x, a.y);
        float2 b = *(const float2*)&w2[o * 64 + 2 * c2];
        *(uint32_t*)(dsm + W2O + o * 144 + c2 * 4) = pack_f16(b.x, b.y);
    }
    // ---- stage pre1 / tline fp16 (once) ----
    for (int f = t; f < 1024; f += 256) {
        int o = f >> 4, w4 = f & 15;
        float4 p = *(const float4*)&g_pre1[bb * 4096 + o * 64 + w4 * 4];
        *(uint2*)(dsm + PRE + o * PRP + w4 * 8) =
            make_uint2(pack_f16(p.x, p.y), pack_f16(p.z, p.w));
        float4 q = *(const float4*)&g_tline[bb * 4096 + o * 64 + w4 * 4];
        *(uint2*)(dsm + TL + o * PRP + w4 * 8) =
            make_uint2(pack_f16(q.x, q.y), pack_f16(q.z, q.w));
    }

    uint32_t aw_base = (uint32_t)(lane & 15) * 144u + (uint32_t)((lane >> 4) * 16);
    uint32_t bx_addr = (uint32_t)(lane & 15) * SVB2
                     + (uint32_t)(vwbase * 2 + (lane >> 4) * 16);

    float bvs[4][2];
    #pragma unroll
    for (int mt = 0; mt < 4; mt++) {
        bvs[mt][0] = __ldg(&b2[16 * mt + r]);
        bvs[mt][1] = __ldg(&b2[16 * mt + r + 8]);
    }

    #pragma unroll 1
    for (int tile = 0; tile < 2; tile++) {
        int m0t = m0 + tile * 128;

        // ---- stage x fp16 [64 c][128 vox] ----
        for (int f = t; f < 1024; f += 256) {
            int cc = f >> 4, v = f & 15;
            const float4* gp = (const float4*)(img + (size_t)(bb * 64 + cc) * M_DIM + m0t)
                             + v * 2;
            float4 x0 = gp[0], x1 = gp[1];
            *(uint4*)(dsm + X16 + cc * SVB2 + v * 16) =
                make_uint4(pack_f16(x0.x, x0.y), pack_f16(x0.z, x0.w),
                           pack_f16(x1.x, x1.y), pack_f16(x1.z, x1.w));
        }
        __syncthreads();   // X (+ first tile: weights/pre/tl) ready

        // ---- acc init from PRE16 ----
        float acc[4][2][4];
        #pragma unroll
        for (int mt = 0; mt < 4; mt++)
            #pragma unroll
            for (int nt = 0; nt < 2; nt++) {
                int ws = (vwbase + 8 * nt + vcol) & 63;
                uint32_t p0 = *(const uint32_t*)(dsm + PRE + (16 * mt + r) * PRP + ws * 2);
                uint32_t p1 = *(const uint32_t*)(dsm + PRE + (16 * mt + r + 8) * PRP + ws * 2);
                float2 f0 = __half22float2(*(__half2*)&p0);
                float2 f1 = __half22float2(*(__half2*)&p1);
                acc[mt][nt][0] = f0.x; acc[mt][nt][1] = f0.y;
                acc[mt][nt][2] = f1.x; acc[mt][nt][3] = f1.y;
            }

        // ---- layer 1 ----
        #pragma unroll
        for (int k = 0; k < 4; k++) {
            uint32_t bx[4];
            ldsm4t(bx, sb + X16 + bx_addr + (uint32_t)(16 * k) * SVB2);
            #pragma unroll
            for (int mt = 0; mt < 4; mt++) {
                uint32_t a[4];
                ldsm4(a, sb + W1O + (uint32_t)(mt * 16) * 144u + aw_base + k * 32u);
                mma_f16(acc[mt][0], a, bx[0], bx[1]);
                mma_f16(acc[mt][1], a, bx[2], bx[3]);
            }
        }

        // ---- relu -> layer2 B-fragments in registers ----
        uint32_t bfr[4][2][2];
        #pragma unroll
        for (int k = 0; k < 4; k++)
            #pragma unroll
            for (int nt = 0; nt < 2; nt++) {
                bfr[k][nt][0] = movm(pack_f16(fmaxf(acc[k][nt][0], 0.f),
                                              fmaxf(acc[k][nt][1], 0.f)));
                bfr[k][nt][1] = movm(pack_f16(fmaxf(acc[k][nt][2], 0.f),
                                              fmaxf(acc[k][nt][3], 0.f)));
            }

        // ---- layer 2 ----
        #pragma unroll
        for (int mt = 0; mt < 4; mt++)
            #pragma unroll
            for (int nt = 0; nt < 2; nt++) {
                acc[mt][nt][0] = bvs[mt][0]; acc[mt][nt][1] = bvs[mt][0];
                acc[mt][nt][2] = bvs[mt][1]; acc[mt][nt][3] = bvs[mt][1];
            }
        #pragma unroll
        for (int k = 0; k < 4; k++) {
            #pragma unroll
            for (int mt = 0; mt < 4; mt++) {
                uint32_t a[4];
                ldsm4(a, sb + W2O + (uint32_t)(mt * 16) * 144u + aw_base + k * 32u);
                mma_f16(acc[mt][0], a, bfr[k][0][0], bfr[k][0][1]);
                mma_f16(acc[mt][1], a, bfr[k][1][0], bfr[k][1][1]);
            }
        }

        // ---- gates -> fp16 GT16 ----
        #pragma unroll
        for (int mt = 0; mt < 4; mt++)
            #pragma unroll
            for (int nt = 0; nt < 2; nt++) {
                int vox0 = vwbase + 8 * nt + vcol;
                *(uint32_t*)(dsm + GT16 + (16 * mt + r) * SVB2 + vox0 * 2) =
                    pack_f16(mufu_sigmoid(acc[mt][nt][0]), mufu_sigmoid(acc[mt][nt][1]));
                *(uint32_t*)(dsm + GT16 + (16 * mt + r + 8) * SVB2 + vox0 * 2) =
                    pack_f16(mufu_sigmoid(acc[mt][nt][2]), mufu_sigmoid(acc[mt][nt][3]));
            }
        __syncthreads();

        // ---- coalesced blend: warp w owns rows 8w..8w+7; vox = lane*4 ----
        #pragma unroll
        for (int jr = 0; jr < 8; jr++) {
            int row = w * 8 + jr;
            size_t gidx = (size_t)(bb * 64 + row) * M_DIM + m0t + lane * 4;
            uint2 xu = *(const uint2*)(dsm + X16 + row * SVB2 + lane * 8);
            uint2 gu = *(const uint2*)(dsm + GT16 + row * SVB2 + lane * 8);
            uint2 tu = *(const uint2*)(dsm + TL + row * PRP + (lane & 15) * 8);
            float2 x0 = __half22float2(*(__half2*)&xu.x);
            float2 x1 = __half22float2(*(__half2*)&xu.y);
            float2 g0 = __half22float2(*(__half2*)&gu.x);
            float2 g1 = __half22float2(*(__half2*)&gu.y);
            float2 t0 = __half22float2(*(__half2*)&tu.x);
            float2 t1 = __half22float2(*(__half2*)&tu.y);
            float4 ov;
            ov.x = fmaf(g0.x, t0.x - x0.x, x0.x);
            ov.y = fmaf(g0.y, t0.y - x0.y, x0.y);
            ov.z = fmaf(g1.x, t1.x - x1.x, x1.x);
            ov.w = fmaf(g1.y, t1.y - x1.y, x1.y);
            *(float4*)(out + gidx) = ov;
        }
        __syncthreads();   // X16/GT16 reads done before next tile overwrites
    }
}

// ================= launch =================
extern "C" void kernel_launch(void* const* d_in, const int* in_sizes, int n_in,
                              void* d_out, int out_size) {
    const float* text = (const float*)d_in[0];
    const float* img  = (const float*)d_in[1];
    const float* w1   = (const float*)d_in[2];
    const float* b1   = (const float*)d_in[3];
    const float* w2   = (const float*)d_in[4];
    const float* b2   = (const float*)d_in[5];
    float* out = (float*)d_out;

    cudaFuncSetAttribute(k_fused, cudaFuncAttributeMaxDynamicSharedMemorySize, 177664);
    cudaFuncSetAttribute(k_mlp,   cudaFuncAttributeMaxDynamicSharedMemorySize, 70656);

    k_fused<<<128, 256, 177664>>>(img, text);
    k_redtl<<<128, 128>>>();
    k_pre1 <<<32, 256>>>(w1, b1);
    k_mlp  <<<1024, 256, 70656>>>(img, w1, w2, b2, out);
}

// round 17
// speedup vs baseline: 1.2590x; 1.0156x over previous
#include <cuda_runtime.h>
#include <cuda_bf16.h>
#include <cuda_fp16.h>
#include <math.h>
#include <stdint.h>

// ---------------- problem constants ----------------
#define L_DIM   128
#define N_DIM   256
#define M_DIM   131072
#define IMG_BSTRIDE 8388608   // 64*131072

// Only n in {4w+1, 4w+2} feed the output. sel s in [0,128): n = 4*(s>>1)+1+(s&1).

// ---------------- scratch (static device memory; no allocs) ----------------
__device__ float g_part[128 * 16384];          // alignedT partials [stripe][sel-n][l]
__device__ float g_tline[2 * 64 * 64];         // [b][c][w]  ([l][w], l = b*64+c)
__device__ float g_pre1[2 * 64 * 64];          // [b][o][w]

// ---------------- MUFU-based fast math ----------------
__device__ __forceinline__ float mufu_sigmoid(float x) {
    float e;
    asm("ex2.approx.f32 %0, %1;" : "=f"(e) : "f"(-1.4426950408889634f * x));
    float r;
    asm("rcp.approx.f32 %0, %1;" : "=f"(r) : "f"(1.0f + e));
    return r;
}
__device__ __forceinline__ float efun(float dot, float an, float bn) {
    float d2 = fmaxf(an + bn - 2.f * dot, 0.f);
    float c;
    asm("sqrt.approx.f32 %0, %1;" : "=f"(c) : "f"(d2));
    float e;
    asm("ex2.approx.f32 %0, %1;" : "=f"(e) : "f"(-0.14426950408889634f * c));
    return 1e-4f * e;
}

// ---------------- warp MMA helpers ----------------
__device__ __forceinline__ uint32_t smem_u32(const void* p) {
    uint32_t a;
    asm("{ .reg .u64 t; cvta.to.shared.u64 t, %1; cvt.u32.u64 %0, t; }" : "=r"(a) : "l"(p));
    return a;
}
__device__ __forceinline__ void ldsm4(uint32_t* r, uint32_t a) {
    asm volatile("ldmatrix.sync.aligned.m8n8.x4.shared.b16 {%0,%1,%2,%3}, [%4];"
                 : "=r"(r[0]), "=r"(r[1]), "=r"(r[2]), "=r"(r[3]) : "r"(a));
}
__device__ __forceinline__ void ldsm4t(uint32_t* r, uint32_t a) {
    asm volatile("ldmatrix.sync.aligned.m8n8.x4.trans.shared.b16 {%0,%1,%2,%3}, [%4];"
                 : "=r"(r[0]), "=r"(r[1]), "=r"(r[2]), "=r"(r[3]) : "r"(a));
}
__device__ __forceinline__ uint32_t movm(uint32_t a) {
    uint32_t d;
    asm volatile("movmatrix.sync.aligned.m8n8.trans.b16 %0, %1;" : "=r"(d) : "r"(a));
    return d;
}
__device__ __forceinline__ void mma_bf16(float* d, const uint32_t* a,
                                         uint32_t b0, uint32_t b1) {
    asm volatile("mma.sync.aligned.m16n8k16.row.col.f32.bf16.bf16.f32 "
                 "{%0,%1,%2,%3}, {%4,%5,%6,%7}, {%8,%9}, {%0,%1,%2,%3};"
                 : "+f"(d[0]), "+f"(d[1]), "+f"(d[2]), "+f"(d[3])
                 : "r"(a[0]), "r"(a[1]), "r"(a[2]), "r"(a[3]), "r"(b0), "r"(b1));
}
__device__ __forceinline__ void mma_f16(float* d, const uint32_t* a,
                                        uint32_t b0, uint32_t b1) {
    asm volatile("mma.sync.aligned.m16n8k16.row.col.f32.f16.f16.f32 "
                 "{%0,%1,%2,%3}, {%4,%5,%6,%7}, {%8,%9}, {%0,%1,%2,%3};"
                 : "+f"(d[0]), "+f"(d[1]), "+f"(d[2]), "+f"(d[3])
                 : "r"(a[0]), "r"(a[1]), "r"(a[2]), "r"(a[3]), "r"(b0), "r"(b1));
}
__device__ __forceinline__ uint32_t pack_bf16(float lo, float hi) {
    uint32_t r;
    asm("cvt.rn.bf16x2.f32 %0, %1, %2;" : "=r"(r) : "f"(hi), "f"(lo));
    return r;
}
__device__ __forceinline__ uint32_t pack_f16(float lo, float hi) {
    uint32_t r;
    asm("cvt.rn.f16x2.f32 %0, %1, %2;" : "=r"(r) : "f"(hi), "f"(lo));
    return r;
}
__device__ __forceinline__ void cp_async16(uint32_t daddr, const void* gptr) {
    asm volatile("cp.async.ca.shared.global [%0], [%1], 16;"
                 :: "r"(daddr), "l"(gptr) : "memory");
}
__device__ __forceinline__ float bf16_hl(uint32_t u, int hi) {
    uint16_t h = hi ? (uint16_t)(u >> 16) : (uint16_t)(u & 0xFFFF);
    return __bfloat162float(__ushort_as_bfloat16(h));
}

// ================= K1: fused pipeline, convert/mma overlap + s-pipelining =====
// 128 CTAs x 256 thr, 1/SM. CTA = m-stripe of 1024 (8 chunks of 128 m).
// Chunk-level: convert c+1 then (no barrier) mma on c. s-level: double-buffered
// bsave, ldsm for s+1 issued before s's mma/efun/movm chain.
// smem: TEXT@0 34816 | STG@34816 67584 | IMGB0@102400 | IMGB1@137216 |
//   TMP@172032 4096 | BN2@176128 1024 (x2) | AN2@177152 512 | total 177664
__global__ __launch_bounds__(256, 1) void k_fused(const float* __restrict__ img,
                                                  const float* __restrict__ text) {
    extern __shared__ char dsm[];
    const int TEXT = 0, STG = 34816, IMGB0 = 102400, IMGB1 = 137216,
              TMP = 172032, BN2 = 176128, AN2 = 177152;
    float* bn2s = (float*)(dsm + BN2);   // [2][128]
    float* an2s = (float*)(dsm + AN2);

    int t = threadIdx.x, bid = blockIdx.x;
    int w = t >> 5, lane = t & 31;
    uint32_t sb = smem_u32(dsm);

    int c4 = t & 31;
    int rp = t >> 5;

    // ---- build text tile + issue chunk 0 ----
    for (int p = t; p < 8192; p += 256) {
        int s = p >> 6, c2 = p & 63;
        int n = 4 * (s >> 1) + 1 + (s & 1);
        *(uint32_t*)(dsm + TEXT + s * 272 + c2 * 4) =
            pack_bf16(__ldg(&text[(2 * c2) * 256 + n]),
                      __ldg(&text[(2 * c2 + 1) * 256 + n]));
    }
    {
        const char* gb = (const char*)(img + (size_t)bid * 1024);
        #pragma unroll
        for (int r = 0; r < 16; r++) {
            int f = t + 256 * r;
            int row = f >> 5, q = f & 31;
            cp_async16(sb + STG + (uint32_t)(row * 33 + q) * 16u,
                       gb + (size_t)row * 524288 + q * 16);
        }
        asm volatile("cp.async.commit_group;" ::: "memory");
    }
    __syncthreads();   // TEXT ready

    if (t < 128) {
        float s = 0.f;
        #pragma unroll 8
        for (int c2 = 0; c2 < 64; c2++) {
            uint32_t u = *(uint32_t*)(dsm + TEXT + t * 272 + c2 * 4);
            float v0 = bf16_hl(u, 0), v1 = bf16_hl(u, 1);
            s = fmaf(v0, v0, fmaf(v1, v1, s));
        }
        an2s[t] = s;
    }
    __syncthreads();   // an2 ready

    uint32_t a_addr = (uint32_t)(w * 16 + (lane & 15)) * 272u
                    + (uint32_t)((lane >> 4) * 16);
    uint32_t atex[8][4];
    #pragma unroll
    for (int kk = 0; kk < 8; kk++)
        ldsm4(atex[kk], sb + TEXT + a_addr + kk * 32u);

    float an2v0 = an2s[w * 16 + (lane >> 2)];
    float an2v1 = an2s[w * 16 + (lane >> 2) + 8];

    float acc2[16][4];
    #pragma unroll
    for (int lt = 0; lt < 16; lt++)
        #pragma unroll
        for (int r = 0; r < 4; r++) acc2[lt][r] = 0.f;

    uint32_t b_row = (uint32_t)(lane & 15) * 272u;
    uint32_t b_colbase = (uint32_t)((lane >> 4) * 16);

    // ---- prologue: convert chunk 0 -> IMGB0 / bn2[0]; issue chunk 1 ----
    asm volatile("cp.async.wait_group 0;" ::: "memory");
    __syncthreads();
    {
        const char* stg = dsm + STG;
        float s0 = 0.f, s1 = 0.f, s2 = 0.f, s3 = 0.f;
        #pragma unroll 8
        for (int i = 0; i < 16; i++) {
            int row = rp + 8 * i;
            float4 v = *(const float4*)(stg + row * 528 + c4 * 16);
            s0 = fmaf(v.x, v.x, s0);
            s1 = fmaf(v.y, v.y, s1);
            s2 = fmaf(v.z, v.z, s2);
            s3 = fmaf(v.w, v.w, s3);
            *(uint2*)(dsm + IMGB0 + row * 272 + c4 * 8) =
                make_uint2(pack_bf16(v.x, v.y), pack_bf16(v.z, v.w));
        }
        ((float4*)(dsm + TMP))[t] = make_float4(s0, s1, s2, s3);
    }
    __syncthreads();
    if (t < 128) {
        float v = 0.f;
        #pragma unroll
        for (int q = 0; q < 8; q++)
            v += ((const float*)(dsm + TMP))[(q * 32 + (t >> 2)) * 4 + (t & 3)];
        bn2s[t] = v;
    }
    {
        const char* gb = (const char*)(img + (size_t)bid * 1024 + 128);
        #pragma unroll
        for (int r = 0; r < 16; r++) {
            int f = t + 256 * r;
            int row = f >> 5, q = f & 31;
            cp_async16(sb + STG + (uint32_t)(row * 33 + q) * 16u,
                       gb + (size_t)row * 524288 + q * 16);
        }
        asm volatile("cp.async.commit_group;" ::: "memory");
    }

    // ---- main loop ----
    #pragma unroll 1
    for (int c = 0; c < 8; c++) {
        if (c < 7) {
            asm volatile("cp.async.wait_group 0;" ::: "memory");
            __syncthreads();   // STG(c+1) visible; IMGB[(c+1)&1] free (mma c-1 done)
            // convert chunk c+1 -> IMGB[(c+1)&1]
            {
                const char* stg = dsm + STG;
                uint32_t ib = ((c + 1) & 1) ? IMGB1 : IMGB0;
                float s0 = 0.f, s1 = 0.f, s2 = 0.f, s3 = 0.f;
                #pragma unroll 8
                for (int i = 0; i < 16; i++) {
                    int row = rp + 8 * i;
                    float4 v = *(const float4*)(stg + row * 528 + c4 * 16);
                    s0 = fmaf(v.x, v.x, s0);
                    s1 = fmaf(v.y, v.y, s1);
                    s2 = fmaf(v.z, v.z, s2);
                    s3 = fmaf(v.w, v.w, s3);
                    *(uint2*)(dsm + ib + row * 272 + c4 * 8) =
                        make_uint2(pack_bf16(v.x, v.y), pack_bf16(v.z, v.w));
                }
                ((float4*)(dsm + TMP))[t] = make_float4(s0, s1, s2, s3);
            }
            __syncthreads();   // TMP ready; STG consumed; bn2[c&1] (prev) visible
            if (t < 128) {
                float v = 0.f;
                #pragma unroll
                for (int q = 0; q < 8; q++)
                    v += ((const float*)(dsm + TMP))[(q * 32 + (t >> 2)) * 4 + (t & 3)];
                bn2s[((c + 1) & 1) * 128 + t] = v;
            }
            if (c < 6) {
                const char* gb = (const char*)(img + (size_t)bid * 1024 + (c + 2) * 128);
                #pragma unroll
                for (int r = 0; r < 16; r++) {
                    int f = t + 256 * r;
                    int row = f >> 5, q = f & 31;
                    cp_async16(sb + STG + (uint32_t)(row * 33 + q) * 16u,
                               gb + (size_t)row * 524288 + q * 16);
                }
                asm volatile("cp.async.commit_group;" ::: "memory");
            }
        } else {
            __syncthreads();   // orders bn2[1] written in iter 6 before mma(7)
        }

        // ---- mma phase on chunk c, software-pipelined over s ----
        uint32_t sbi = sb + ((c & 1) ? IMGB1 : IMGB0);
        const float* bnp = bn2s + (c & 1) * 128;

        uint32_t bsA[8][4], bsB[8][4];
        #pragma unroll
        for (int kk = 0; kk < 8; kk++)
            ldsm4t(bsA[kk], sbi + b_row + (uint32_t)(kk * 16) * 272u + b_colbase);

        #pragma unroll
        for (int s = 0; s < 8; s++) {
            uint32_t (*cur)[4] = (s & 1) ? bsB : bsA;
            uint32_t (*nxt)[4] = (s & 1) ? bsA : bsB;

            // prefetch s+1's B fragments before the dependent chain of s
            if (s < 7) {
                uint32_t scoln = (uint32_t)((s + 1) * 32) + b_colbase;
                #pragma unroll
                for (int kk = 0; kk < 8; kk++)
                    ldsm4t(nxt[kk], sbi + b_row + (uint32_t)(kk * 16) * 272u + scoln);
            }

            float c1[2][4];
            #pragma unroll
            for (int j = 0; j < 2; j++)
                #pragma unroll
                for (int r = 0; r < 4; r++) c1[j][r] = 0.f;

            #pragma unroll
            for (int kk = 0; kk < 8; kk++) {
                mma_bf16(c1[0], atex[kk], cur[kk][0], cur[kk][1]);
                mma_bf16(c1[1], atex[kk], cur[kk][2], cur[kk][3]);
            }

            uint32_t a2[4];
            #pragma unroll
            for (int j = 0; j < 2; j++) {
                float2 bn = *(float2*)&bnp[s * 16 + j * 8 + 2 * (lane & 3)];
                float e0 = efun(c1[j][0], an2v0, bn.x);
                float e1 = efun(c1[j][1], an2v0, bn.y);
                float e2 = efun(c1[j][2], an2v1, bn.x);
                float e3 = efun(c1[j][3], an2v1, bn.y);
                a2[2 * j]     = pack_bf16(e0, e1);
                a2[2 * j + 1] = pack_bf16(e2, e3);
            }

            #pragma unroll
            for (int lb = 0; lb < 8; lb++) {
                uint32_t m0r = movm(cur[lb][0]);
                uint32_t m1r = movm(cur[lb][1]);
                uint32_t m2r = movm(cur[lb][2]);
                uint32_t m3r = movm(cur[lb][3]);
                mma_bf16(acc2[2 * lb],     a2, m0r, m2r);
                mma_bf16(acc2[2 * lb + 1], a2, m1r, m3r);
            }
        }
    }

    // store partials: g_part[bid][sel-n][l]
    int nbase = w * 16 + (lane >> 2);
    #pragma unroll
    for (int lt = 0; lt < 16; lt++) {
        int l = lt * 8 + 2 * (lane & 3);
        size_t base = (size_t)bid * 16384 + (size_t)nbase * 128 + l;
        *(float2*)&g_part[base] = make_float2(acc2[lt][0], acc2[lt][1]);
        *(float2*)&g_part[base + 8 * 128] = make_float2(acc2[lt][2], acc2[lt][3]);
    }
}

// ================= K2: split-K reduce partials + interp -> t_line =============
__global__ void k_redtl() {
    __shared__ float4 red[128];
    int t = threadIdx.x, B = blockIdx.x;
    int out = B * 16 + (t & 15);
    int split = t >> 4;
    int w = out >> 5, l4 = out & 31;
    const float4* p4 = (const float4*)g_part;
    float4 s = make_float4(0.f, 0.f, 0.f, 0.f);
    #pragma unroll 4
    for (int st = split * 16; st < split * 16 + 16; st++) {
        float4 a = p4[(size_t)st * 4096 + (2 * w) * 32 + l4];
        float4 b = p4[(size_t)st * 4096 + (2 * w + 1) * 32 + l4];
        s.x += a.x + b.x; s.y += a.y + b.y;
        s.z += a.z + b.z; s.w += a.w + b.w;
    }
    red[t] = s;
    __syncthreads();
    if (t < 16) {
        float4 s2 = red[t];
        #pragma unroll
        for (int q = 1; q < 8; q++) {
            float4 r = red[t + 16 * q];
            s2.x += r.x; s2.y += r.y; s2.z += r.z; s2.w += r.w;
        }
        int o2 = B * 16 + t;
        int w2 = o2 >> 5, l42 = o2 & 31;
        g_tline[(4 * l42 + 0) * 64 + w2] = 0.5f * s2.x;
        g_tline[(4 * l42 + 1) * 64 + w2] = 0.5f * s2.y;
        g_tline[(4 * l42 + 2) * 64 + w2] = 0.5f * s2.z;
        g_tline[(4 * l42 + 3) * 64 + w2] = 0.5f * s2.w;
    }
}

// ================= K3: pre1 = b1 + W1a @ t_line =================
__global__ void k_pre1(const float* __restrict__ w1, const float* __restrict__ b1) {
    int f = blockIdx.x * 256 + threadIdx.x;
    int b = f >> 12, o = (f >> 6) & 63, w = f & 63;
    float s = __ldg(&b1[o]);
    #pragma unroll 8
    for (int c = 0; c < 64; c++)
        s = fmaf(__ldg(&w1[o * 128 + c]), g_tline[(b * 64 + c) * 64 + w], s);
    g_pre1[f] = s;
}

// ================= K4: MLP, register-resident H, 2 tiles per block ============
#define SVB2 272
#define PRP  136
__global__ __launch_bounds__(256, 3) void k_mlp(const float* __restrict__ img,
                                                const float* __restrict__ w1,
                                                const float* __restrict__ w2,
                                                const float* __restrict__ b2,
                                                float* __restrict__ out) {
    extern __shared__ char dsm[];
    const int X16 = 0, GT16 = 17408, W1O = 34816, W2O = 44032,
              PRE = 53248, TL = 61952;
    uint32_t sb = smem_u32(dsm);

    int t = threadIdx.x;
    int bb = blockIdx.x >> 9;
    int m0 = (blockIdx.x & 511) << 8;
    int w = t >> 5, lane = t & 31;
    int vwbase = w * 16;
    int r = lane >> 2;
    int vcol = 2 * (lane & 3);

    for (int f = t; f < 2048; f += 256) {
        int o = f >> 5, c2 = f & 31;
        float2 a = *(const float2*)&w1[o * 128 + 64 + 2 * c2];
        *(uint32_t*)(dsm + W1O + o * 144 + c2 * 4) = pack_f16(a.x, a.y);
        float2 b = *(const float2*)&w2[o * 64 + 2 * c2];
        *(uint32_t*)(dsm + W2O + o * 144 + c2 * 4) = pack_f16(b.x, b.y);
    }
    for (int f = t; f < 1024; f += 256) {
        int o = f >> 4, w4 = f & 15;
        float4 p = *(const float4*)&g_pre1[bb * 4096 + o * 64 + w4 * 4];
        *(uint2*)(dsm + PRE + o * PRP + w4 * 8) =
            make_uint2(pack_f16(p.x, p.y), pack_f16(p.z, p.w));
        float4 q = *(const float4*)&g_tline[bb * 4096 + o * 64 + w4 * 4];
        *(uint2*)(dsm + TL + o * PRP + w4 * 8) =
            make_uint2(pack_f16(q.x, q.y), pack_f16(q.z, q.w));
    }

    uint32_t aw_base = (uint32_t)(lane & 15) * 144u + (uint32_t)((lane >> 4) * 16);
    uint32_t bx_addr = (uint32_t)(lane & 15) * SVB2
                     + (uint32_t)(vwbase * 2 + (lane >> 4) * 16);

    float bvs[4][2];
    #pragma unroll
    for (int mt = 0; mt < 4; mt++) {
        bvs[mt][0] = __ldg(&b2[16 * mt + r]);
        bvs[mt][1] = __ldg(&b2[16 * mt + r + 8]);
    }

    #pragma unroll 1
    for (int tile = 0; tile < 2; tile++) {
        int m0t = m0 + tile * 128;

        for (int f = t; f < 1024; f += 256) {
            int cc = f >> 4, v = f & 15;
            const float4* gp = (const float4*)(img + (size_t)(bb * 64 + cc) * M_DIM + m0t)
                             + v * 2;
            float4 x0 = gp[0], x1 = gp[1];
            *(uint4*)(dsm + X16 + cc * SVB2 + v * 16) =
                make_uint4(pack_f16(x0.x, x0.y), pack_f16(x0.z, x0.w),
                           pack_f16(x1.x, x1.y), pack_f16(x1.z, x1.w));
        }
        __syncthreads();

        float acc[4][2][4];
        #pragma unroll
        for (int mt = 0; mt < 4; mt++)
            #pragma unroll
            for (int nt = 0; nt < 2; nt++) {
                int ws = (vwbase + 8 * nt + vcol) & 63;
                uint32_t p0 = *(const uint32_t*)(dsm + PRE + (16 * mt + r) * PRP + ws * 2);
                uint32_t p1 = *(const uint32_t*)(dsm + PRE + (16 * mt + r + 8) * PRP + ws * 2);
                float2 f0 = __half22float2(*(__half2*)&p0);
                float2 f1 = __half22float2(*(__half2*)&p1);
                acc[mt][nt][0] = f0.x; acc[mt][nt][1] = f0.y;
                acc[mt][nt][2] = f1.x; acc[mt][nt][3] = f1.y;
            }

        #pragma unroll
        for (int k = 0; k < 4; k++) {
            uint32_t bx[4];
            ldsm4t(bx, sb + X16 + bx_addr + (uint32_t)(16 * k) * SVB2);
            #pragma unroll
            for (int mt = 0; mt < 4; mt++) {
                uint32_t a[4];
                ldsm4(a, sb + W1O + (uint32_t)(mt * 16) * 144u + aw_base + k * 32u);
                mma_f16(acc[mt][0], a, bx[0], bx[1]);
                mma_f16(acc[mt][1], a, bx[2], bx[3]);
            }
        }

        uint32_t bfr[4][2][2];
        #pragma unroll
        for (int k = 0; k < 4; k++)
            #pragma unroll
            for (int nt = 0; nt < 2; nt++) {
                bfr[k][nt][0] = movm(pack_f16(fmaxf(acc[k][nt][0], 0.f),
                                              fmaxf(acc[k][nt][1], 0.f)));
                bfr[k][nt][1] = movm(pack_f16(fmaxf(acc[k][nt][2], 0.f),
                                              fmaxf(acc[k][nt][3], 0.f)));
            }

        #pragma unroll
        for (int mt = 0; mt < 4; mt++)
            #pragma unroll
            for (int nt = 0; nt < 2; nt++) {
                acc[mt][nt][0] = bvs[mt][0]; acc[mt][nt][1] = bvs[mt][0];
                acc[mt][nt][2] = bvs[mt][1]; acc[mt][nt][3] = bvs[mt][1];
            }
        #pragma unroll
        for (int k = 0; k < 4; k++) {
            #pragma unroll
            for (int mt = 0; mt < 4; mt++) {
                uint32_t a[4];
                ldsm4(a, sb + W2O + (uint32_t)(mt * 16) * 144u + aw_base + k * 32u);
                mma_f16(acc[mt][0], a, bfr[k][0][0], bfr[k][0][1]);
                mma_f16(acc[mt][1], a, bfr[k][1][0], bfr[k][1][1]);
            }
        }

        #pragma unroll
        for (int mt = 0; mt < 4; mt++)
            #pragma unroll
            for (int nt = 0; nt < 2; nt++) {
                int vox0 = vwbase + 8 * nt + vcol;
                *(uint32_t*)(dsm + GT16 + (16 * mt + r) * SVB2 + vox0 * 2) =
                    pack_f16(mufu_sigmoid(acc[mt][nt][0]), mufu_sigmoid(acc[mt][nt][1]));
                *(uint32_t*)(dsm + GT16 + (16 * mt + r + 8) * SVB2 + vox0 * 2) =
                    pack_f16(mufu_sigmoid(acc[mt][nt][2]), mufu_sigmoid(acc[mt][nt][3]));
            }
        __syncthreads();

        #pragma unroll
        for (int jr = 0; jr < 8; jr++) {
            int row = w * 8 + jr;
            size_t gidx = (size_t)(bb * 64 + row) * M_DIM + m0t + lane * 4;
            uint2 xu = *(const uint2*)(dsm + X16 + row * SVB2 + lane * 8);
            uint2 gu = *(const uint2*)(dsm + GT16 + row * SVB2 + lane * 8);
            uint2 tu = *(const uint2*)(dsm + TL + row * PRP + (lane & 15) * 8);
            float2 x0 = __half22float2(*(__half2*)&xu.x);
            float2 x1 = __half22float2(*(__half2*)&xu.y);
            float2 g0 = __half22float2(*(__half2*)&gu.x);
            float2 g1 = __half22float2(*(__half2*)&gu.y);
            float2 t0 = __half22float2(*(__half2*)&tu.x);
            float2 t1 = __half22float2(*(__half2*)&tu.y);
            float4 ov;
            ov.x = fmaf(g0.x, t0.x - x0.x, x0.x);
            ov.y = fmaf(g0.y, t0.y - x0.y, x0.y);
            ov.z = fmaf(g1.x, t1.x - x1.x, x1.x);
            ov.w = fmaf(g1.y, t1.y - x1.y, x1.y);
            *(float4*)(out + gidx) = ov;
        }
        __syncthreads();
    }
}

// ================= launch =================
extern "C" void kernel_launch(void* const* d_in, const int* in_sizes, int n_in,
                              void* d_out, int out_size) {
    const float* text = (const float*)d_in[0];
    const float* img  = (const float*)d_in[1];
    const float* w1   = (const float*)d_in[2];
    const float* b1   = (const float*)d_in[3];
    const float* w2   = (const float*)d_in[4];
    const float* b2   = (const float*)d_in[5];
    float* out = (float*)d_out;

    cudaFuncSetAttribute(k_fused, cudaFuncAttributeMaxDynamicSharedMemorySize, 177664);
    cudaFuncSetAttribute(k_mlp,   cudaFuncAttributeMaxDynamicSharedMemorySize, 70656);

    k_fused<<<128, 256, 177664>>>(img, text);
    k_redtl<<<128, 128>>>();
    k_pre1 <<<32, 256>>>(w1, b1);
    k_mlp  <<<1024, 256, 70656>>>(img, w1, w2, b2, out);
}